// round 1
// baseline (speedup 1.0000x reference)
#include <cuda_runtime.h>
#include <math_constants.h>

// Problem constants (fixed by the reference setup)
#define NN  50000
#define DD  512
#define HH  512
#define OC  256
#define EE  150000

// ---------------- scratch (no allocation allowed -> __device__ globals) ----------------
__device__ float g_hsrc[(size_t)NN * HH];   // layer1: [N,512]; layer2 reuse: [N,256]
__device__ float g_hdst[(size_t)NN * HH];
__device__ float g_agg [(size_t)NN * HH];   // conv accumulator (init to 2*bias)
__device__ float g_hmid[(size_t)NN * HH];   // after lin1
__device__ float g_asrc[NN];
__device__ float g_adst[NN];
__device__ float g_m[NN];
__device__ float g_s[NN];
__device__ float g_e[EE];
__device__ float g_wa[DD];
__device__ float g_wb[DD];

// ---------------- SGEMM: C = A[MxK] @ B[KxN] (+bias) (optional relu) ----------------
// BM=BN=128, BK=8, TM=TN=8, 256 threads.
template<bool BIAS, bool RELU>
__global__ __launch_bounds__(256, 2)
void sgemm_kernel(const float* __restrict__ A, const float* __restrict__ Bm,
                  const float* __restrict__ bias, float* __restrict__ C,
                  int M, int N, int K)
{
    const int BM = 128, BN = 128, BK = 8, TM = 8, TN = 8;
    __shared__ float As[BK][BM];
    __shared__ float Bs[BK][BN];

    int tid = threadIdx.x;
    int tx = tid & 15;          // 0..15 -> col group
    int ty = tid >> 4;          // 0..15 -> row group

    int aRow = tid >> 1;        // 0..127
    int aCol = (tid & 1) << 2;  // 0 or 4
    int bRow = tid >> 5;        // 0..7
    int bCol = (tid & 31) << 2; // 0..124

    long rowA = (long)blockIdx.y * BM + aRow;
    bool aValid = rowA < (long)M;
    const float* Aptr = A + (aValid ? rowA * (long)K : 0) + aCol;
    const float* Bptr = Bm + (size_t)bRow * N + (size_t)blockIdx.x * BN + bCol;

    float acc[TM][TN];
    #pragma unroll
    for (int i = 0; i < TM; i++)
        #pragma unroll
        for (int j = 0; j < TN; j++) acc[i][j] = 0.f;

    for (int kt = 0; kt < K; kt += BK) {
        float4 av = aValid ? *(const float4*)Aptr : make_float4(0.f, 0.f, 0.f, 0.f);
        Aptr += BK;
        float4 bv = *(const float4*)Bptr;
        Bptr += (size_t)BK * N;

        As[aCol + 0][aRow] = av.x;
        As[aCol + 1][aRow] = av.y;
        As[aCol + 2][aRow] = av.z;
        As[aCol + 3][aRow] = av.w;
        *(float4*)&Bs[bRow][bCol] = bv;
        __syncthreads();

        #pragma unroll
        for (int k = 0; k < BK; k++) {
            float ra[TM], rb[TN];
            #pragma unroll
            for (int i = 0; i < TM; i++) ra[i] = As[k][ty * TM + i];
            #pragma unroll
            for (int j = 0; j < TN; j++) rb[j] = Bs[k][tx * TN + j];
            #pragma unroll
            for (int i = 0; i < TM; i++)
                #pragma unroll
                for (int j = 0; j < TN; j++)
                    acc[i][j] = fmaf(ra[i], rb[j], acc[i][j]);
        }
        __syncthreads();
    }

    int colBase = blockIdx.x * BN + tx * TN;
    #pragma unroll
    for (int i = 0; i < TM; i++) {
        long row = (long)blockIdx.y * BM + ty * TM + i;
        if (row < (long)M) {
            float* cp = C + row * (long)N + colBase;
            #pragma unroll
            for (int j = 0; j < TN; j += 4) {
                float4 v;
                v.x = acc[i][j + 0]; v.y = acc[i][j + 1];
                v.z = acc[i][j + 2]; v.w = acc[i][j + 3];
                if (BIAS) {
                    v.x += bias[colBase + j + 0];
                    v.y += bias[colBase + j + 1];
                    v.z += bias[colBase + j + 2];
                    v.w += bias[colBase + j + 3];
                }
                if (RELU) {
                    v.x = fmaxf(v.x, 0.f); v.y = fmaxf(v.y, 0.f);
                    v.z = fmaxf(v.z, 0.f); v.w = fmaxf(v.w, 0.f);
                }
                *(float4*)(cp + j) = v;
            }
        }
    }
}

// ---------------- GEMV: out[m] = A[m,:] . v  (warp per row, K % 128 == 0) ----------------
__global__ void gemv_kernel(const float* __restrict__ A, const float* __restrict__ v,
                            float* __restrict__ out, int M, int K)
{
    int row = blockIdx.x * (blockDim.x >> 5) + (threadIdx.x >> 5);
    int lane = threadIdx.x & 31;
    if (row >= M) return;
    const float4* a4 = (const float4*)(A + (size_t)row * K);
    const float4* v4 = (const float4*)v;
    int K4 = K >> 2;
    float sum = 0.f;
    for (int k = lane; k < K4; k += 32) {
        float4 a = a4[k], b = v4[k];
        sum += a.x * b.x + a.y * b.y + a.z * b.z + a.w * b.w;
    }
    #pragma unroll
    for (int o = 16; o; o >>= 1) sum += __shfl_down_sync(0xffffffffu, sum, o);
    if (lane == 0) out[row] = sum;
}

// ---------------- edge / segment-softmax kernels ----------------
__device__ __forceinline__ void atomicMaxFloat(float* addr, float val)
{
    if (val >= 0.f) atomicMax((int*)addr, __float_as_int(val));
    else            atomicMin((unsigned int*)addr, __float_as_uint(val));
}

__global__ void init_ms_kernel(float* __restrict__ m, float* __restrict__ s, int n)
{
    int i = blockIdx.x * blockDim.x + threadIdx.x;
    if (i < n) { m[i] = -CUDART_INF_F; s[i] = 0.f; }
}

__global__ void init_agg_kernel(float* __restrict__ agg, const float* __restrict__ b,
                                int total, int Cmask)
{
    int idx = blockIdx.x * blockDim.x + threadIdx.x;
    if (idx < total) agg[idx] = 2.f * b[idx & Cmask];
}

__global__ void edge_max_kernel(const int* __restrict__ src, const int* __restrict__ dst,
                                const float* __restrict__ as_, const float* __restrict__ ad_,
                                float* __restrict__ e, float* __restrict__ m, int E)
{
    int i = blockIdx.x * blockDim.x + threadIdx.x;
    if (i >= E) return;
    float v = as_[src[i]] + ad_[dst[i]];
    v = v > 0.f ? v : 0.2f * v;      // leaky_relu, slope 0.2
    e[i] = v;
    atomicMaxFloat(&m[dst[i]], v);
}

__global__ void edge_exp_kernel(const int* __restrict__ dst, float* __restrict__ e,
                                const float* __restrict__ m, float* __restrict__ s, int E)
{
    int i = blockIdx.x * blockDim.x + threadIdx.x;
    if (i >= E) return;
    int d = dst[i];
    float ex = expf(e[i] - m[d]);
    e[i] = ex;
    atomicAdd(&s[d], ex);
}

// one block per edge; blockDim = C/4; float4 gather of h_src[src], atomic scatter to out[dst]
__global__ void edge_scatter_kernel(const int* __restrict__ src, const int* __restrict__ dst,
                                    const float* __restrict__ e, const float* __restrict__ s,
                                    const float* __restrict__ h, float* __restrict__ out, int C)
{
    int i = blockIdx.x;
    int sn = src[i], dn = dst[i];
    float w = e[i] / (s[dn] + 1e-16f);
    const float4* hp = (const float4*)(h + (size_t)sn * C);
    float* op = out + (size_t)dn * C;
    int c = threadIdx.x;
    float4 hv = hp[c];
    atomicAdd(op + 4 * c + 0, w * hv.x);
    atomicAdd(op + 4 * c + 1, w * hv.y);
    atomicAdd(op + 4 * c + 2, w * hv.z);
    atomicAdd(op + 4 * c + 3, w * hv.w);
}

// ---------------- host orchestration ----------------
static float* symaddr(const void* s)
{
    void* p = nullptr;
    cudaGetSymbolAddress(&p, s);
    return (float*)p;
}

extern "C" void kernel_launch(void* const* d_in, const int* in_sizes, int n_in,
                              void* d_out, int out_size)
{
    (void)n_in; (void)out_size;
    const float* x   = (const float*)d_in[0];
    const int*   ei1 = (const int*)d_in[1];
    const int*   ei2 = (const int*)d_in[2];
    const float* W1s = (const float*)d_in[3];
    const float* W1d = (const float*)d_in[4];
    const float* a1s = (const float*)d_in[5];
    const float* a1d = (const float*)d_in[6];
    const float* b1  = (const float*)d_in[7];
    const float* Wl1 = (const float*)d_in[8];
    const float* bl1 = (const float*)d_in[9];
    const float* W2s = (const float*)d_in[10];
    const float* W2d = (const float*)d_in[11];
    const float* a2s = (const float*)d_in[12];
    const float* a2d = (const float*)d_in[13];
    const float* b2  = (const float*)d_in[14];
    const float* Wl2 = (const float*)d_in[15];
    const float* bl2 = (const float*)d_in[16];
    float* out = (float*)d_out;

    const int N = in_sizes[0] / DD;       // 50000
    const int E = in_sizes[1] / 2;        // 150000

    float* hsrc = symaddr(g_hsrc);
    float* hdst = symaddr(g_hdst);
    float* agg  = symaddr(g_agg);
    float* hmid = symaddr(g_hmid);
    float* asrc = symaddr(g_asrc);
    float* adst = symaddr(g_adst);
    float* mm   = symaddr(g_m);
    float* ss   = symaddr(g_s);
    float* ee   = symaddr(g_e);
    float* wa   = symaddr(g_wa);
    float* wb   = symaddr(g_wb);

    dim3 gH(HH / 128, (N + 127) / 128);   // N-dim 512 GEMM grid
    dim3 gO(OC / 128, (N + 127) / 128);   // N-dim 256 GEMM grid

    // ================= layer 1 (D=512 -> H=512) =================
    // alpha vectors: wa = W1_src @ a1_src ; wb = W1_dst @ a1_dst
    gemv_kernel<<<(DD + 7) / 8, 256>>>(W1s, a1s, wa, DD, HH);
    gemv_kernel<<<(DD + 7) / 8, 256>>>(W1d, a1d, wb, DD, HH);
    // h_src / h_dst (shared by both edge lists)
    sgemm_kernel<false, false><<<gH, 256>>>(x, W1s, nullptr, hsrc, N, HH, DD);
    sgemm_kernel<false, false><<<gH, 256>>>(x, W1d, nullptr, hdst, N, HH, DD);
    // alpha_src = x @ wa ; alpha_dst = x @ wb
    gemv_kernel<<<(N + 7) / 8, 256>>>(x, wa, asrc, N, DD);
    gemv_kernel<<<(N + 7) / 8, 256>>>(x, wb, adst, N, DD);
    // accumulator = 2*b1 (one bias per conv)
    init_agg_kernel<<<(N * HH + 255) / 256, 256>>>(agg, b1, N * HH, HH - 1);

    for (int l = 0; l < 2; l++) {
        const int* srcp = (l ? ei2 : ei1);
        const int* dstp = srcp + E;
        init_ms_kernel<<<(N + 255) / 256, 256>>>(mm, ss, N);
        edge_max_kernel<<<(E + 255) / 256, 256>>>(srcp, dstp, asrc, adst, ee, mm, E);
        edge_exp_kernel<<<(E + 255) / 256, 256>>>(dstp, ee, mm, ss, E);
        edge_scatter_kernel<<<E, HH / 4>>>(srcp, dstp, ee, ss, hsrc, agg, HH);
    }

    // hmid = relu(agg @ Wl1 + bl1)
    sgemm_kernel<true, true><<<gH, 256>>>(agg, Wl1, bl1, hmid, N, HH, HH);

    // ================= layer 2 (H=512 -> O=256) =================
    gemv_kernel<<<(HH + 7) / 8, 256>>>(W2s, a2s, wa, HH, OC);
    gemv_kernel<<<(HH + 7) / 8, 256>>>(W2d, a2d, wb, HH, OC);
    sgemm_kernel<false, false><<<gO, 256>>>(hmid, W2s, nullptr, hsrc, N, OC, HH);
    sgemm_kernel<false, false><<<gO, 256>>>(hmid, W2d, nullptr, hdst, N, OC, HH);
    gemv_kernel<<<(N + 7) / 8, 256>>>(hmid, wa, asrc, N, HH);
    gemv_kernel<<<(N + 7) / 8, 256>>>(hmid, wb, adst, N, HH);
    init_agg_kernel<<<(N * OC + 255) / 256, 256>>>(agg, b2, N * OC, OC - 1);

    for (int l = 0; l < 2; l++) {
        const int* srcp = (l ? ei2 : ei1);
        const int* dstp = srcp + E;
        init_ms_kernel<<<(N + 255) / 256, 256>>>(mm, ss, N);
        edge_max_kernel<<<(E + 255) / 256, 256>>>(srcp, dstp, asrc, adst, ee, mm, E);
        edge_exp_kernel<<<(E + 255) / 256, 256>>>(dstp, ee, mm, ss, E);
        edge_scatter_kernel<<<E, OC / 4>>>(srcp, dstp, ee, ss, hsrc, agg, OC);
    }

    // out = agg @ Wl2 + bl2
    sgemm_kernel<true, false><<<gO, 256>>>(agg, Wl2, bl2, out, N, OC, OC);
}

// round 2
// speedup vs baseline: 1.4625x; 1.4625x over previous
#include <cuda_runtime.h>
#include <math_constants.h>

// Problem constants (fixed by the reference setup)
#define NN  50000
#define DD  512
#define HH  512
#define OC  256
#define EE  150000

// ---------------- scratch (no allocation allowed -> __device__ globals) ----------------
__device__ float g_hsrc[(size_t)NN * HH];   // layer1: [N,512]; layer2 reuse: [N,256]
__device__ float g_agg [(size_t)NN * HH];   // conv accumulator (init to 2*bias)
__device__ float g_hmid[(size_t)NN * HH];   // after lin1
__device__ float g_asrc[NN];
__device__ float g_adst[NN];
__device__ float g_m[NN];
__device__ float g_s[NN];
__device__ float g_e[EE];
__device__ float g_wa[DD];
__device__ float g_wb[DD];

// ---------------- SGEMM: C = A[MxK] @ B[KxN] (+bias) (optional relu) ----------------
// BM=BN=128, BK=16, TM=TN=8, 256 threads, double-buffered shared memory.
template<bool BIAS, bool RELU>
__global__ __launch_bounds__(256, 2)
void sgemm_kernel(const float* __restrict__ A, const float* __restrict__ Bm,
                  const float* __restrict__ bias, float* __restrict__ C,
                  int M, int N, int K)
{
    const int BM = 128, BN = 128, BK = 16, TM = 8, TN = 8;
    __shared__ float As[2][BK][BM];
    __shared__ float Bs[2][BK][BN];

    int tid = threadIdx.x;
    int tx = tid & 15;            // 0..15 -> col group
    int ty = tid >> 4;            // 0..15 -> row group

    int aRow = tid >> 1;          // 0..127
    int aK   = (tid & 1) << 2;    // 0 or 4  (second load at +8)
    int bRow = tid >> 5;          // 0..7    (second load at +8)
    int bCol = (tid & 31) << 2;   // 0..124

    long rowA = (long)blockIdx.y * BM + aRow;
    bool aValid = rowA < (long)M;
    const float* Aptr = A + (aValid ? rowA * (long)K : 0);
    const float* Bptr = Bm + (size_t)blockIdx.x * BN + bCol;

    const float4 z4 = make_float4(0.f, 0.f, 0.f, 0.f);

    // ---- prologue: tile 0 -> buffer 0 ----
    float4 a0 = aValid ? *(const float4*)(Aptr + aK)     : z4;
    float4 a1 = aValid ? *(const float4*)(Aptr + aK + 8) : z4;
    float4 b0 = *(const float4*)(Bptr + (size_t)bRow * N);
    float4 b1 = *(const float4*)(Bptr + (size_t)(bRow + 8) * N);

    As[0][aK + 0][aRow] = a0.x;  As[0][aK + 1][aRow] = a0.y;
    As[0][aK + 2][aRow] = a0.z;  As[0][aK + 3][aRow] = a0.w;
    As[0][aK + 8][aRow] = a1.x;  As[0][aK + 9][aRow] = a1.y;
    As[0][aK + 10][aRow] = a1.z; As[0][aK + 11][aRow] = a1.w;
    *(float4*)&Bs[0][bRow][bCol]     = b0;
    *(float4*)&Bs[0][bRow + 8][bCol] = b1;
    __syncthreads();

    float acc[TM][TN];
    #pragma unroll
    for (int i = 0; i < TM; i++)
        #pragma unroll
        for (int j = 0; j < TN; j++) acc[i][j] = 0.f;

    int nTiles = K / BK;
    for (int t = 0; t < nTiles; t++) {
        int cur = t & 1, nxt = cur ^ 1;

        // issue global loads for tile t+1 (overlap with compute)
        if (t + 1 < nTiles) {
            const float* Ap = Aptr + (size_t)(t + 1) * BK;
            const float* Bp = Bptr + (size_t)(t + 1) * BK * N;
            a0 = aValid ? *(const float4*)(Ap + aK)     : z4;
            a1 = aValid ? *(const float4*)(Ap + aK + 8) : z4;
            b0 = *(const float4*)(Bp + (size_t)bRow * N);
            b1 = *(const float4*)(Bp + (size_t)(bRow + 8) * N);
        }

        #pragma unroll
        for (int k = 0; k < BK; k++) {
            float ra[TM], rb[TN];
            *(float4*)(ra + 0) = *(const float4*)&As[cur][k][ty * TM + 0];
            *(float4*)(ra + 4) = *(const float4*)&As[cur][k][ty * TM + 4];
            *(float4*)(rb + 0) = *(const float4*)&Bs[cur][k][tx * TN + 0];
            *(float4*)(rb + 4) = *(const float4*)&Bs[cur][k][tx * TN + 4];
            #pragma unroll
            for (int i = 0; i < TM; i++)
                #pragma unroll
                for (int j = 0; j < TN; j++)
                    acc[i][j] = fmaf(ra[i], rb[j], acc[i][j]);
        }

        if (t + 1 < nTiles) {
            As[nxt][aK + 0][aRow] = a0.x;  As[nxt][aK + 1][aRow] = a0.y;
            As[nxt][aK + 2][aRow] = a0.z;  As[nxt][aK + 3][aRow] = a0.w;
            As[nxt][aK + 8][aRow] = a1.x;  As[nxt][aK + 9][aRow] = a1.y;
            As[nxt][aK + 10][aRow] = a1.z; As[nxt][aK + 11][aRow] = a1.w;
            *(float4*)&Bs[nxt][bRow][bCol]     = b0;
            *(float4*)&Bs[nxt][bRow + 8][bCol] = b1;
            __syncthreads();
        }
    }

    int colBase = blockIdx.x * BN + tx * TN;
    #pragma unroll
    for (int i = 0; i < TM; i++) {
        long row = (long)blockIdx.y * BM + ty * TM + i;
        if (row < (long)M) {
            float* cp = C + row * (long)N + colBase;
            #pragma unroll
            for (int j = 0; j < TN; j += 4) {
                float4 v;
                v.x = acc[i][j + 0]; v.y = acc[i][j + 1];
                v.z = acc[i][j + 2]; v.w = acc[i][j + 3];
                if (BIAS) {
                    v.x += bias[colBase + j + 0];
                    v.y += bias[colBase + j + 1];
                    v.z += bias[colBase + j + 2];
                    v.w += bias[colBase + j + 3];
                }
                if (RELU) {
                    v.x = fmaxf(v.x, 0.f); v.y = fmaxf(v.y, 0.f);
                    v.z = fmaxf(v.z, 0.f); v.w = fmaxf(v.w, 0.f);
                }
                *(float4*)(cp + j) = v;
            }
        }
    }
}

// ---------------- GEMV: out[m] = A[m,:] . v  (warp per row, K % 128 == 0) ----------------
__global__ void gemv_kernel(const float* __restrict__ A, const float* __restrict__ v,
                            float* __restrict__ out, int M, int K)
{
    int row = blockIdx.x * (blockDim.x >> 5) + (threadIdx.x >> 5);
    int lane = threadIdx.x & 31;
    if (row >= M) return;
    const float4* a4 = (const float4*)(A + (size_t)row * K);
    const float4* v4 = (const float4*)v;
    int K4 = K >> 2;
    float sum = 0.f;
    for (int k = lane; k < K4; k += 32) {
        float4 a = a4[k], b = v4[k];
        sum += a.x * b.x + a.y * b.y + a.z * b.z + a.w * b.w;
    }
    #pragma unroll
    for (int o = 16; o; o >>= 1) sum += __shfl_down_sync(0xffffffffu, sum, o);
    if (lane == 0) out[row] = sum;
}

// ---------------- edge / segment-softmax kernels ----------------
__device__ __forceinline__ void atomicMaxFloat(float* addr, float val)
{
    if (val >= 0.f) atomicMax((int*)addr, __float_as_int(val));
    else            atomicMin((unsigned int*)addr, __float_as_uint(val));
}

__global__ void init_ms_kernel(float* __restrict__ m, float* __restrict__ s, int n)
{
    int i = blockIdx.x * blockDim.x + threadIdx.x;
    if (i < n) { m[i] = -CUDART_INF_F; s[i] = 0.f; }
}

__global__ void init_agg_kernel(float* __restrict__ agg, const float* __restrict__ b,
                                int total, int Cmask)
{
    int idx = blockIdx.x * blockDim.x + threadIdx.x;
    if (idx < total) agg[idx] = 2.f * b[idx & Cmask];
}

__global__ void edge_max_kernel(const int* __restrict__ src, const int* __restrict__ dst,
                                const float* __restrict__ as_, const float* __restrict__ ad_,
                                float* __restrict__ e, float* __restrict__ m, int E)
{
    int i = blockIdx.x * blockDim.x + threadIdx.x;
    if (i >= E) return;
    float v = as_[src[i]] + ad_[dst[i]];
    v = v > 0.f ? v : 0.2f * v;      // leaky_relu, slope 0.2
    e[i] = v;
    atomicMaxFloat(&m[dst[i]], v);
}

__global__ void edge_exp_kernel(const int* __restrict__ dst, float* __restrict__ e,
                                const float* __restrict__ m, float* __restrict__ s, int E)
{
    int i = blockIdx.x * blockDim.x + threadIdx.x;
    if (i >= E) return;
    int d = dst[i];
    float ex = expf(e[i] - m[d]);
    e[i] = ex;
    atomicAdd(&s[d], ex);
}

// one block per edge; blockDim = C/4; float4 gather of h_src[src], atomic scatter to out[dst]
__global__ void edge_scatter_kernel(const int* __restrict__ src, const int* __restrict__ dst,
                                    const float* __restrict__ e, const float* __restrict__ s,
                                    const float* __restrict__ h, float* __restrict__ out, int C)
{
    int i = blockIdx.x;
    int sn = src[i], dn = dst[i];
    float w = e[i] / (s[dn] + 1e-16f);
    const float4* hp = (const float4*)(h + (size_t)sn * C);
    float* op = out + (size_t)dn * C;
    int c = threadIdx.x;
    float4 hv = hp[c];
    atomicAdd(op + 4 * c + 0, w * hv.x);
    atomicAdd(op + 4 * c + 1, w * hv.y);
    atomicAdd(op + 4 * c + 2, w * hv.z);
    atomicAdd(op + 4 * c + 3, w * hv.w);
}

// ---------------- host orchestration ----------------
static float* symaddr(const void* s)
{
    void* p = nullptr;
    cudaGetSymbolAddress(&p, s);
    return (float*)p;
}

extern "C" void kernel_launch(void* const* d_in, const int* in_sizes, int n_in,
                              void* d_out, int out_size)
{
    (void)n_in; (void)out_size;
    const float* x   = (const float*)d_in[0];
    const int*   ei1 = (const int*)d_in[1];
    const int*   ei2 = (const int*)d_in[2];
    const float* W1s = (const float*)d_in[3];
    const float* W1d = (const float*)d_in[4];
    const float* a1s = (const float*)d_in[5];
    const float* a1d = (const float*)d_in[6];
    const float* b1  = (const float*)d_in[7];
    const float* Wl1 = (const float*)d_in[8];
    const float* bl1 = (const float*)d_in[9];
    const float* W2s = (const float*)d_in[10];
    const float* W2d = (const float*)d_in[11];
    const float* a2s = (const float*)d_in[12];
    const float* a2d = (const float*)d_in[13];
    const float* b2  = (const float*)d_in[14];
    const float* Wl2 = (const float*)d_in[15];
    const float* bl2 = (const float*)d_in[16];
    float* out = (float*)d_out;

    const int N = in_sizes[0] / DD;       // 50000
    const int E = in_sizes[1] / 2;        // 150000

    float* hsrc = symaddr(g_hsrc);
    float* agg  = symaddr(g_agg);
    float* hmid = symaddr(g_hmid);
    float* asrc = symaddr(g_asrc);
    float* adst = symaddr(g_adst);
    float* mm   = symaddr(g_m);
    float* ss   = symaddr(g_s);
    float* ee   = symaddr(g_e);
    float* wa   = symaddr(g_wa);
    float* wb   = symaddr(g_wb);

    dim3 gH(HH / 128, (N + 127) / 128);   // N-dim 512 GEMM grid
    dim3 gO(OC / 128, (N + 127) / 128);   // N-dim 256 GEMM grid

    // ================= layer 1 (D=512 -> H=512) =================
    // alpha projection vectors: wa = W1_src @ a1_src ; wb = W1_dst @ a1_dst
    // NOTE: h_dst is NEVER materialized — it only feeds alpha_dst = x @ (W_dst @ a_dst).
    gemv_kernel<<<(DD + 7) / 8, 256>>>(W1s, a1s, wa, DD, HH);
    gemv_kernel<<<(DD + 7) / 8, 256>>>(W1d, a1d, wb, DD, HH);
    // h_src (shared by both edge lists)
    sgemm_kernel<false, false><<<gH, 256>>>(x, W1s, nullptr, hsrc, N, HH, DD);
    // alpha_src = x @ wa ; alpha_dst = x @ wb
    gemv_kernel<<<(N + 7) / 8, 256>>>(x, wa, asrc, N, DD);
    gemv_kernel<<<(N + 7) / 8, 256>>>(x, wb, adst, N, DD);
    // accumulator = 2*b1 (one bias per conv)
    init_agg_kernel<<<(N * HH + 255) / 256, 256>>>(agg, b1, N * HH, HH - 1);

    for (int l = 0; l < 2; l++) {
        const int* srcp = (l ? ei2 : ei1);
        const int* dstp = srcp + E;
        init_ms_kernel<<<(N + 255) / 256, 256>>>(mm, ss, N);
        edge_max_kernel<<<(E + 255) / 256, 256>>>(srcp, dstp, asrc, adst, ee, mm, E);
        edge_exp_kernel<<<(E + 255) / 256, 256>>>(dstp, ee, mm, ss, E);
        edge_scatter_kernel<<<E, HH / 4>>>(srcp, dstp, ee, ss, hsrc, agg, HH);
    }

    // hmid = relu(agg @ Wl1 + bl1)
    sgemm_kernel<true, true><<<gH, 256>>>(agg, Wl1, bl1, hmid, N, HH, HH);

    // ================= layer 2 (H=512 -> O=256) =================
    gemv_kernel<<<(HH + 7) / 8, 256>>>(W2s, a2s, wa, HH, OC);
    gemv_kernel<<<(HH + 7) / 8, 256>>>(W2d, a2d, wb, HH, OC);
    sgemm_kernel<false, false><<<gO, 256>>>(hmid, W2s, nullptr, hsrc, N, OC, HH);
    gemv_kernel<<<(N + 7) / 8, 256>>>(hmid, wa, asrc, N, HH);
    gemv_kernel<<<(N + 7) / 8, 256>>>(hmid, wb, adst, N, HH);
    init_agg_kernel<<<(N * OC + 255) / 256, 256>>>(agg, b2, N * OC, OC - 1);

    for (int l = 0; l < 2; l++) {
        const int* srcp = (l ? ei2 : ei1);
        const int* dstp = srcp + E;
        init_ms_kernel<<<(N + 255) / 256, 256>>>(mm, ss, N);
        edge_max_kernel<<<(E + 255) / 256, 256>>>(srcp, dstp, asrc, adst, ee, mm, E);
        edge_exp_kernel<<<(E + 255) / 256, 256>>>(dstp, ee, mm, ss, E);
        edge_scatter_kernel<<<E, OC / 4>>>(srcp, dstp, ee, ss, hsrc, agg, OC);
    }

    // out = agg @ Wl2 + bl2
    sgemm_kernel<true, false><<<gO, 256>>>(agg, Wl2, bl2, out, N, OC, OC);
}

// round 3
// speedup vs baseline: 2.4817x; 1.6969x over previous
#include <cuda_runtime.h>
#include <cuda_bf16.h>
#include <math_constants.h>
#include <cstdint>

// Problem constants (fixed by the reference setup)
#define NN  50000
#define DD  512
#define HH  512
#define OC  256
#define EE  150000

// ---------------- scratch (no allocation allowed -> __device__ globals) ----------------
__device__ float g_hsrc[(size_t)NN * HH];   // layer1: [N,512]; layer2 reuse: [N,256]
__device__ float g_agg [(size_t)NN * HH];   // conv accumulator (init to 2*bias)
__device__ float g_hmid[(size_t)NN * HH];   // after lin1
__device__ float g_asrc[NN];
__device__ float g_adst[NN];
__device__ float g_m[NN];
__device__ float g_s[NN];
__device__ float g_e[EE];
__device__ float g_wa[DD];
__device__ float g_wb[DD];

// ---------------- tensor-core GEMM: C = A[MxK] @ B[KxN] (+bias)(+relu) ----------------
// 3-term bf16 split (Ahi*Bhi + Ahi*Blo + Alo*Bhi) with fp32 accumulate -> ~fp32 accuracy.
// BM=128, BN=128, BK=32, 256 threads (8 warps as 4x2), mma.sync m16n8k16.

#define LDM4(r0,r1,r2,r3,addr) \
    asm volatile("ldmatrix.sync.aligned.m8n8.x4.shared.b16 {%0,%1,%2,%3}, [%4];" \
                 : "=r"(r0),"=r"(r1),"=r"(r2),"=r"(r3) : "r"(addr))
#define LDM4T(r0,r1,r2,r3,addr) \
    asm volatile("ldmatrix.sync.aligned.m8n8.x4.trans.shared.b16 {%0,%1,%2,%3}, [%4];" \
                 : "=r"(r0),"=r"(r1),"=r"(r2),"=r"(r3) : "r"(addr))
#define MMA16816(d, a, b) \
    asm volatile("mma.sync.aligned.m16n8k16.row.col.f32.bf16.bf16.f32 " \
                 "{%0,%1,%2,%3},{%4,%5,%6,%7},{%8,%9},{%0,%1,%2,%3};" \
                 : "+f"(d[0]),"+f"(d[1]),"+f"(d[2]),"+f"(d[3]) \
                 : "r"(a[0]),"r"(a[1]),"r"(a[2]),"r"(a[3]),"r"(b[0]),"r"(b[1]))

__device__ __forceinline__ uint32_t smem_u32(const void* p)
{
    return (uint32_t)__cvta_generic_to_shared(p);
}

// split two floats into bf16 hi pair + bf16 lo (residual) pair, store as bf16x2
__device__ __forceinline__ void split2(__nv_bfloat16* hp, __nv_bfloat16* lp, float x, float y)
{
    __nv_bfloat162 h = __floats2bfloat162_rn(x, y);
    float2 hf = __bfloat1622float2(h);
    __nv_bfloat162 l = __floats2bfloat162_rn(x - hf.x, y - hf.y);
    *(__nv_bfloat162*)hp = h;
    *(__nv_bfloat162*)lp = l;
}

template<bool BIAS, bool RELU>
__global__ __launch_bounds__(256)
void mma_gemm_kernel(const float* __restrict__ A, const float* __restrict__ Bm,
                     const float* __restrict__ bias, float* __restrict__ C,
                     int M, int N, int K)
{
    const int BM = 128, BN = 128, BK = 32;
    const int APAD = 8, BPAD = 8;     // row strides: A 40 el (80B), B 136 el (272B) -> ldmatrix conflict-free
    __shared__ __align__(16) __nv_bfloat16 sAhi[BM][BK + APAD];
    __shared__ __align__(16) __nv_bfloat16 sAlo[BM][BK + APAD];
    __shared__ __align__(16) __nv_bfloat16 sBhi[BK][BN + BPAD];
    __shared__ __align__(16) __nv_bfloat16 sBlo[BK][BN + BPAD];

    int tid = threadIdx.x;
    int lane = tid & 31;
    int w = tid >> 5;
    int wm = w & 3;          // 4 warps along M (32 rows each)
    int wn = w >> 2;         // 2 warps along N (64 cols each)

    int blockM = blockIdx.y * BM;
    int blockN = blockIdx.x * BN;

    // global tile load mapping
    int aRow0 = tid >> 3;          // + 32*i
    int aCol  = (tid & 7) * 4;
    int bRow0 = tid >> 5;          // + 8*i
    int bCol  = (tid & 31) * 4;

    const float4 z4 = make_float4(0.f, 0.f, 0.f, 0.f);
    float4 pa[4], pb[4];

    float acc[2][8][4];
    #pragma unroll
    for (int mt = 0; mt < 2; mt++)
        #pragma unroll
        for (int nt = 0; nt < 8; nt++)
            #pragma unroll
            for (int q = 0; q < 4; q++) acc[mt][nt][q] = 0.f;

    uint32_t baseAhi = smem_u32(&sAhi[0][0]);
    uint32_t baseAlo = smem_u32(&sAlo[0][0]);
    uint32_t baseBhi = smem_u32(&sBhi[0][0]);
    uint32_t baseBlo = smem_u32(&sBlo[0][0]);

    // prologue: tile 0
    #pragma unroll
    for (int i = 0; i < 4; i++) {
        int r = blockM + aRow0 + 32 * i;
        pa[i] = (r < M) ? *(const float4*)(A + (size_t)r * K + aCol) : z4;
        pb[i] = *(const float4*)(Bm + (size_t)(bRow0 + 8 * i) * N + blockN + bCol);
    }
    #pragma unroll
    for (int i = 0; i < 4; i++) {
        int r = aRow0 + 32 * i;
        split2(&sAhi[r][aCol],     &sAlo[r][aCol],     pa[i].x, pa[i].y);
        split2(&sAhi[r][aCol + 2], &sAlo[r][aCol + 2], pa[i].z, pa[i].w);
        int br = bRow0 + 8 * i;
        split2(&sBhi[br][bCol],     &sBlo[br][bCol],     pb[i].x, pb[i].y);
        split2(&sBhi[br][bCol + 2], &sBlo[br][bCol + 2], pb[i].z, pb[i].w);
    }
    __syncthreads();

    int nT = K / BK;
    for (int kt = 0; kt < nT; kt++) {
        // prefetch next tile to registers (overlaps with mma phase)
        if (kt + 1 < nT) {
            #pragma unroll
            for (int i = 0; i < 4; i++) {
                int r = blockM + aRow0 + 32 * i;
                pa[i] = (r < M) ? *(const float4*)(A + (size_t)r * K + (kt + 1) * BK + aCol) : z4;
                pb[i] = *(const float4*)(Bm + (size_t)((kt + 1) * BK + bRow0 + 8 * i) * N + blockN + bCol);
            }
        }

        // compute on current smem tile
        #pragma unroll
        for (int ks = 0; ks < 2; ks++) {
            uint32_t ah[2][4], al[2][4];
            #pragma unroll
            for (int mt = 0; mt < 2; mt++) {
                uint32_t off = (uint32_t)((wm * 32 + mt * 16 + (lane & 15)) * (BK + APAD)
                                          + (lane >> 4) * 8 + ks * 16) * 2u;
                LDM4(ah[mt][0], ah[mt][1], ah[mt][2], ah[mt][3], baseAhi + off);
                LDM4(al[mt][0], al[mt][1], al[mt][2], al[mt][3], baseAlo + off);
            }
            uint32_t bh[8][2], bl[8][2];
            #pragma unroll
            for (int p = 0; p < 4; p++) {
                uint32_t off = (uint32_t)((ks * 16 + (lane & 15)) * (BN + BPAD)
                                          + wn * 64 + p * 16 + ((lane & 16) >> 1)) * 2u;
                uint32_t r0, r1, r2, r3;
                LDM4T(r0, r1, r2, r3, baseBhi + off);
                bh[2 * p][0] = r0; bh[2 * p][1] = r1;
                bh[2 * p + 1][0] = r2; bh[2 * p + 1][1] = r3;
                LDM4T(r0, r1, r2, r3, baseBlo + off);
                bl[2 * p][0] = r0; bl[2 * p][1] = r1;
                bl[2 * p + 1][0] = r2; bl[2 * p + 1][1] = r3;
            }
            #pragma unroll
            for (int mt = 0; mt < 2; mt++)
                #pragma unroll
                for (int nt = 0; nt < 8; nt++) {
                    MMA16816(acc[mt][nt], ah[mt], bh[nt]);
                    MMA16816(acc[mt][nt], ah[mt], bl[nt]);
                    MMA16816(acc[mt][nt], al[mt], bh[nt]);
                }
        }
        __syncthreads();

        if (kt + 1 < nT) {
            #pragma unroll
            for (int i = 0; i < 4; i++) {
                int r = aRow0 + 32 * i;
                split2(&sAhi[r][aCol],     &sAlo[r][aCol],     pa[i].x, pa[i].y);
                split2(&sAhi[r][aCol + 2], &sAlo[r][aCol + 2], pa[i].z, pa[i].w);
                int br = bRow0 + 8 * i;
                split2(&sBhi[br][bCol],     &sBlo[br][bCol],     pb[i].x, pb[i].y);
                split2(&sBhi[br][bCol + 2], &sBlo[br][bCol + 2], pb[i].z, pb[i].w);
            }
            __syncthreads();
        }
    }

    // epilogue
    #pragma unroll
    for (int mt = 0; mt < 2; mt++) {
        #pragma unroll
        for (int nt = 0; nt < 8; nt++) {
            int row = blockM + wm * 32 + mt * 16 + (lane >> 2);
            int col = blockN + wn * 64 + nt * 8 + (lane & 3) * 2;
            float2 v0 = make_float2(acc[mt][nt][0], acc[mt][nt][1]);
            float2 v1 = make_float2(acc[mt][nt][2], acc[mt][nt][3]);
            if (BIAS) {
                float2 bv = *(const float2*)(bias + col);
                v0.x += bv.x; v0.y += bv.y;
                v1.x += bv.x; v1.y += bv.y;
            }
            if (RELU) {
                v0.x = fmaxf(v0.x, 0.f); v0.y = fmaxf(v0.y, 0.f);
                v1.x = fmaxf(v1.x, 0.f); v1.y = fmaxf(v1.y, 0.f);
            }
            if (row < M)     *(float2*)(C + (size_t)row * N + col) = v0;
            if (row + 8 < M) *(float2*)(C + (size_t)(row + 8) * N + col) = v1;
        }
    }
}

// ---------------- GEMV: out[m] = A[m,:] . v  (warp per row) ----------------
__global__ void gemv_kernel(const float* __restrict__ A, const float* __restrict__ v,
                            float* __restrict__ out, int M, int K)
{
    int row = blockIdx.x * (blockDim.x >> 5) + (threadIdx.x >> 5);
    int lane = threadIdx.x & 31;
    if (row >= M) return;
    const float4* a4 = (const float4*)(A + (size_t)row * K);
    const float4* v4 = (const float4*)v;
    int K4 = K >> 2;
    float sum = 0.f;
    for (int k = lane; k < K4; k += 32) {
        float4 a = a4[k], b = v4[k];
        sum += a.x * b.x + a.y * b.y + a.z * b.z + a.w * b.w;
    }
    #pragma unroll
    for (int o = 16; o; o >>= 1) sum += __shfl_down_sync(0xffffffffu, sum, o);
    if (lane == 0) out[row] = sum;
}

// dual GEMV: oa[m] = A[m,:].va, ob[m] = A[m,:].vb — reads A once
__global__ void gemv2_kernel(const float* __restrict__ A,
                             const float* __restrict__ va, const float* __restrict__ vb,
                             float* __restrict__ oa, float* __restrict__ ob, int M, int K)
{
    int row = blockIdx.x * (blockDim.x >> 5) + (threadIdx.x >> 5);
    int lane = threadIdx.x & 31;
    if (row >= M) return;
    const float4* a4 = (const float4*)(A + (size_t)row * K);
    const float4* va4 = (const float4*)va;
    const float4* vb4 = (const float4*)vb;
    int K4 = K >> 2;
    float sa = 0.f, sb = 0.f;
    for (int k = lane; k < K4; k += 32) {
        float4 a = a4[k], u = va4[k], t = vb4[k];
        sa += a.x * u.x + a.y * u.y + a.z * u.z + a.w * u.w;
        sb += a.x * t.x + a.y * t.y + a.z * t.z + a.w * t.w;
    }
    #pragma unroll
    for (int o = 16; o; o >>= 1) {
        sa += __shfl_down_sync(0xffffffffu, sa, o);
        sb += __shfl_down_sync(0xffffffffu, sb, o);
    }
    if (lane == 0) { oa[row] = sa; ob[row] = sb; }
}

// ---------------- edge / segment-softmax kernels ----------------
__device__ __forceinline__ void atomicMaxFloat(float* addr, float val)
{
    if (val >= 0.f) atomicMax((int*)addr, __float_as_int(val));
    else            atomicMin((unsigned int*)addr, __float_as_uint(val));
}

__global__ void init_ms_kernel(float* __restrict__ m, float* __restrict__ s, int n)
{
    int i = blockIdx.x * blockDim.x + threadIdx.x;
    if (i < n) { m[i] = -CUDART_INF_F; s[i] = 0.f; }
}

__global__ void init_agg_kernel(float* __restrict__ agg, const float* __restrict__ b,
                                int total, int Cmask)
{
    int idx = blockIdx.x * blockDim.x + threadIdx.x;
    if (idx < total) agg[idx] = 2.f * b[idx & Cmask];
}

__global__ void edge_max_kernel(const int* __restrict__ src, const int* __restrict__ dst,
                                const float* __restrict__ as_, const float* __restrict__ ad_,
                                float* __restrict__ e, float* __restrict__ m, int E)
{
    int i = blockIdx.x * blockDim.x + threadIdx.x;
    if (i >= E) return;
    float v = as_[src[i]] + ad_[dst[i]];
    v = v > 0.f ? v : 0.2f * v;      // leaky_relu, slope 0.2
    e[i] = v;
    atomicMaxFloat(&m[dst[i]], v);
}

__global__ void edge_exp_kernel(const int* __restrict__ dst, float* __restrict__ e,
                                const float* __restrict__ m, float* __restrict__ s, int E)
{
    int i = blockIdx.x * blockDim.x + threadIdx.x;
    if (i >= E) return;
    int d = dst[i];
    float ex = expf(e[i] - m[d]);
    e[i] = ex;
    atomicAdd(&s[d], ex);
}

// one block per edge; blockDim = C/4; float4 gather of h_src[src], atomic scatter to out[dst]
__global__ void edge_scatter_kernel(const int* __restrict__ src, const int* __restrict__ dst,
                                    const float* __restrict__ e, const float* __restrict__ s,
                                    const float* __restrict__ h, float* __restrict__ out, int C)
{
    int i = blockIdx.x;
    int sn = src[i], dn = dst[i];
    float w = e[i] / (s[dn] + 1e-16f);
    const float4* hp = (const float4*)(h + (size_t)sn * C);
    float* op = out + (size_t)dn * C;
    int c = threadIdx.x;
    float4 hv = hp[c];
    atomicAdd(op + 4 * c + 0, w * hv.x);
    atomicAdd(op + 4 * c + 1, w * hv.y);
    atomicAdd(op + 4 * c + 2, w * hv.z);
    atomicAdd(op + 4 * c + 3, w * hv.w);
}

// ---------------- host orchestration ----------------
static float* symaddr(const void* s)
{
    void* p = nullptr;
    cudaGetSymbolAddress(&p, s);
    return (float*)p;
}

extern "C" void kernel_launch(void* const* d_in, const int* in_sizes, int n_in,
                              void* d_out, int out_size)
{
    (void)n_in; (void)out_size;
    const float* x   = (const float*)d_in[0];
    const int*   ei1 = (const int*)d_in[1];
    const int*   ei2 = (const int*)d_in[2];
    const float* W1s = (const float*)d_in[3];
    const float* W1d = (const float*)d_in[4];
    const float* a1s = (const float*)d_in[5];
    const float* a1d = (const float*)d_in[6];
    const float* b1  = (const float*)d_in[7];
    const float* Wl1 = (const float*)d_in[8];
    const float* bl1 = (const float*)d_in[9];
    const float* W2s = (const float*)d_in[10];
    const float* W2d = (const float*)d_in[11];
    const float* a2s = (const float*)d_in[12];
    const float* a2d = (const float*)d_in[13];
    const float* b2  = (const float*)d_in[14];
    const float* Wl2 = (const float*)d_in[15];
    const float* bl2 = (const float*)d_in[16];
    float* out = (float*)d_out;

    const int N = in_sizes[0] / DD;       // 50000
    const int E = in_sizes[1] / 2;        // 150000

    float* hsrc = symaddr(g_hsrc);
    float* agg  = symaddr(g_agg);
    float* hmid = symaddr(g_hmid);
    float* asrc = symaddr(g_asrc);
    float* adst = symaddr(g_adst);
    float* mm   = symaddr(g_m);
    float* ss   = symaddr(g_s);
    float* ee   = symaddr(g_e);
    float* wa   = symaddr(g_wa);
    float* wb   = symaddr(g_wb);

    dim3 gH(HH / 128, (N + 127) / 128);   // 512-col GEMM grid
    dim3 gO(OC / 128, (N + 127) / 128);   // 256-col GEMM grid

    // ================= layer 1 (D=512 -> H=512) =================
    // alpha projection vectors: wa = W1_src @ a1_src ; wb = W1_dst @ a1_dst
    // h_dst is never materialized — it only feeds alpha_dst = x @ (W_dst @ a_dst).
    gemv_kernel<<<(DD + 7) / 8, 256>>>(W1s, a1s, wa, DD, HH);
    gemv_kernel<<<(DD + 7) / 8, 256>>>(W1d, a1d, wb, DD, HH);
    // h_src (shared by both edge lists)
    mma_gemm_kernel<false, false><<<gH, 256>>>(x, W1s, nullptr, hsrc, N, HH, DD);
    // alpha_src = x @ wa ; alpha_dst = x @ wb (single pass over x)
    gemv2_kernel<<<(N + 7) / 8, 256>>>(x, wa, wb, asrc, adst, N, DD);
    // accumulator = 2*b1 (one bias per conv)
    init_agg_kernel<<<(N * HH + 255) / 256, 256>>>(agg, b1, N * HH, HH - 1);

    for (int l = 0; l < 2; l++) {
        const int* srcp = (l ? ei2 : ei1);
        const int* dstp = srcp + E;
        init_ms_kernel<<<(N + 255) / 256, 256>>>(mm, ss, N);
        edge_max_kernel<<<(E + 255) / 256, 256>>>(srcp, dstp, asrc, adst, ee, mm, E);
        edge_exp_kernel<<<(E + 255) / 256, 256>>>(dstp, ee, mm, ss, E);
        edge_scatter_kernel<<<E, HH / 4>>>(srcp, dstp, ee, ss, hsrc, agg, HH);
    }

    // hmid = relu(agg @ Wl1 + bl1)
    mma_gemm_kernel<true, true><<<gH, 256>>>(agg, Wl1, bl1, hmid, N, HH, HH);

    // ================= layer 2 (H=512 -> O=256) =================
    gemv_kernel<<<(HH + 7) / 8, 256>>>(W2s, a2s, wa, HH, OC);
    gemv_kernel<<<(HH + 7) / 8, 256>>>(W2d, a2d, wb, HH, OC);
    mma_gemm_kernel<false, false><<<gO, 256>>>(hmid, W2s, nullptr, hsrc, N, OC, HH);
    gemv2_kernel<<<(N + 7) / 8, 256>>>(hmid, wa, wb, asrc, adst, N, HH);
    init_agg_kernel<<<(N * OC + 255) / 256, 256>>>(agg, b2, N * OC, OC - 1);

    for (int l = 0; l < 2; l++) {
        const int* srcp = (l ? ei2 : ei1);
        const int* dstp = srcp + E;
        init_ms_kernel<<<(N + 255) / 256, 256>>>(mm, ss, N);
        edge_max_kernel<<<(E + 255) / 256, 256>>>(srcp, dstp, asrc, adst, ee, mm, E);
        edge_exp_kernel<<<(E + 255) / 256, 256>>>(dstp, ee, mm, ss, E);
        edge_scatter_kernel<<<E, OC / 4>>>(srcp, dstp, ee, ss, hsrc, agg, OC);
    }

    // out = agg @ Wl2 + bl2
    mma_gemm_kernel<true, false><<<gO, 256>>>(agg, Wl2, bl2, out, N, OC, OC);
}

// round 6
// speedup vs baseline: 3.7105x; 1.4952x over previous
#include <cuda_runtime.h>
#include <cuda_bf16.h>
#include <math_constants.h>
#include <cstdint>

// Problem constants (fixed by the reference setup)
#define NN  50000
#define DD  512
#define HH  512
#define OC  256
#define EE  150000

// ---------------- scratch (no allocation allowed -> __device__ globals) ----------------
__device__ float g_hsrc[(size_t)NN * HH];   // layer1: [N,512]; layer2 reuse: [N,256]
__device__ float g_agg [(size_t)NN * HH];   // conv accumulator
__device__ float g_hmid[(size_t)NN * HH];   // after lin1
__device__ float g_asrc[NN];
__device__ float g_adst[NN];
__device__ float g_s[2][NN];                // per-list softmax sums
__device__ float g_wa[DD];
__device__ float g_wb[DD];

// CSR structures (built once per launch; shared by both layers)
__device__ int   g_rowptr[2][NN + 1];
__device__ int   g_pos[2][NN];              // histogram, then fill cursor
__device__ int   g_perm[2][EE];             // edge -> csr slot
__device__ int   g_csrc[2][EE];             // csr: source node per slot
__device__ float g_cw[2][EE];               // csr: exp(e) per slot (per layer)
__device__ int   g_bsum[2][128];
__device__ int   g_boff[2][128];

// pre-split weights, [K,N] fp32 layout -> bf16 hi/lo (same layout)
#define WO1 0
#define WO2 262144
#define WO3 524288
#define WO4 655360
#define WTOT 720896
__device__ __nv_bfloat16 g_whi[WTOT];
__device__ __nv_bfloat16 g_wlo[WTOT];

// ==================== weight bf16 hi/lo split (elementwise, float4) ====================
__global__ void wsplit_kernel(const float* __restrict__ W,
                              __nv_bfloat16* __restrict__ hi, __nv_bfloat16* __restrict__ lo,
                              int total4)
{
    int i = blockIdx.x * blockDim.x + threadIdx.x;
    if (i >= total4) return;
    float4 v = ((const float4*)W)[i];
    __nv_bfloat162 h0 = __floats2bfloat162_rn(v.x, v.y);
    float2 f0 = __bfloat1622float2(h0);
    __nv_bfloat162 l0 = __floats2bfloat162_rn(v.x - f0.x, v.y - f0.y);
    __nv_bfloat162 h1 = __floats2bfloat162_rn(v.z, v.w);
    float2 f1 = __bfloat1622float2(h1);
    __nv_bfloat162 l1 = __floats2bfloat162_rn(v.z - f1.x, v.w - f1.y);
    uint2 hh, ll;
    hh.x = reinterpret_cast<uint32_t&>(h0); hh.y = reinterpret_cast<uint32_t&>(h1);
    ll.x = reinterpret_cast<uint32_t&>(l0); ll.y = reinterpret_cast<uint32_t&>(l1);
    ((uint2*)hi)[i] = hh;
    ((uint2*)lo)[i] = ll;
}

// ==================== tensor-core GEMM (mma.sync, 3-term bf16 split) ====================
#define LDM4(r0,r1,r2,r3,addr) \
    asm volatile("ldmatrix.sync.aligned.m8n8.x4.shared.b16 {%0,%1,%2,%3}, [%4];" \
                 : "=r"(r0),"=r"(r1),"=r"(r2),"=r"(r3) : "r"(addr))
#define LDM4T(r0,r1,r2,r3,addr) \
    asm volatile("ldmatrix.sync.aligned.m8n8.x4.trans.shared.b16 {%0,%1,%2,%3}, [%4];" \
                 : "=r"(r0),"=r"(r1),"=r"(r2),"=r"(r3) : "r"(addr))
#define MMA16816(d, a, b) \
    asm volatile("mma.sync.aligned.m16n8k16.row.col.f32.bf16.bf16.f32 " \
                 "{%0,%1,%2,%3},{%4,%5,%6,%7},{%8,%9},{%0,%1,%2,%3};" \
                 : "+f"(d[0]),"+f"(d[1]),"+f"(d[2]),"+f"(d[3]) \
                 : "r"(a[0]),"r"(a[1]),"r"(a[2]),"r"(a[3]),"r"(b[0]),"r"(b[1]))

__device__ __forceinline__ uint32_t smem_u32(const void* p)
{
    return (uint32_t)__cvta_generic_to_shared(p);
}

__device__ __forceinline__ void split2(__nv_bfloat16* hp, __nv_bfloat16* lp, float x, float y)
{
    __nv_bfloat162 h = __floats2bfloat162_rn(x, y);
    float2 hf = __bfloat1622float2(h);
    __nv_bfloat162 l = __floats2bfloat162_rn(x - hf.x, y - hf.y);
    *(__nv_bfloat162*)hp = h;
    *(__nv_bfloat162*)lp = l;
}

// C = A[MxK](fp32, split on the fly) @ B[KxN](pre-split bf16 hi/lo) (+bias)(+relu)
template<bool BIAS, bool RELU>
__global__ __launch_bounds__(256)
void mma_gemm_kernel(const float* __restrict__ A,
                     const __nv_bfloat16* __restrict__ Bhi,
                     const __nv_bfloat16* __restrict__ Blo,
                     const float* __restrict__ bias, float* __restrict__ C,
                     int M, int N, int K)
{
    const int BM = 128, BN = 128, BK = 32;
    const int APAD = 8, BPAD = 8;
    __shared__ __align__(16) __nv_bfloat16 sAhi[BM][BK + APAD];
    __shared__ __align__(16) __nv_bfloat16 sAlo[BM][BK + APAD];
    __shared__ __align__(16) __nv_bfloat16 sBhi[BK][BN + BPAD];
    __shared__ __align__(16) __nv_bfloat16 sBlo[BK][BN + BPAD];

    int tid = threadIdx.x;
    int lane = tid & 31;
    int w = tid >> 5;
    int wm = w & 3;
    int wn = w >> 2;

    int blockM = blockIdx.y * BM;
    int blockN = blockIdx.x * BN;

    int aRow0 = tid >> 3;          // + 32*i
    int aCol  = (tid & 7) * 4;
    // B tile: 32 rows x 128 cols = 512 uint4-groups of 8 bf16; 2 groups per thread
    int bR[2], bC[2];
    #pragma unroll
    for (int i = 0; i < 2; i++) {
        int g = tid + 256 * i;
        bR[i] = g >> 4;            // 0..31
        bC[i] = (g & 15) * 8;      // 0..120
    }

    const float4 z4 = make_float4(0.f, 0.f, 0.f, 0.f);
    float4 pa[4];
    uint4 pbh[2], pbl[2];

    float acc[2][8][4];
    #pragma unroll
    for (int mt = 0; mt < 2; mt++)
        #pragma unroll
        for (int nt = 0; nt < 8; nt++)
            #pragma unroll
            for (int q = 0; q < 4; q++) acc[mt][nt][q] = 0.f;

    uint32_t baseAhi = smem_u32(&sAhi[0][0]);
    uint32_t baseAlo = smem_u32(&sAlo[0][0]);
    uint32_t baseBhi = smem_u32(&sBhi[0][0]);
    uint32_t baseBlo = smem_u32(&sBlo[0][0]);

    // prologue: tile 0
    #pragma unroll
    for (int i = 0; i < 4; i++) {
        int r = blockM + aRow0 + 32 * i;
        pa[i] = (r < M) ? *(const float4*)(A + (size_t)r * K + aCol) : z4;
    }
    #pragma unroll
    for (int i = 0; i < 2; i++) {
        size_t go = (size_t)bR[i] * N + blockN + bC[i];
        pbh[i] = *(const uint4*)(Bhi + go);
        pbl[i] = *(const uint4*)(Blo + go);
    }
    #pragma unroll
    for (int i = 0; i < 4; i++) {
        int r = aRow0 + 32 * i;
        split2(&sAhi[r][aCol],     &sAlo[r][aCol],     pa[i].x, pa[i].y);
        split2(&sAhi[r][aCol + 2], &sAlo[r][aCol + 2], pa[i].z, pa[i].w);
    }
    #pragma unroll
    for (int i = 0; i < 2; i++) {
        *(uint4*)&sBhi[bR[i]][bC[i]] = pbh[i];
        *(uint4*)&sBlo[bR[i]][bC[i]] = pbl[i];
    }
    __syncthreads();

    int nT = K / BK;
    for (int kt = 0; kt < nT; kt++) {
        // prefetch next tile to registers
        if (kt + 1 < nT) {
            #pragma unroll
            for (int i = 0; i < 4; i++) {
                int r = blockM + aRow0 + 32 * i;
                pa[i] = (r < M) ? *(const float4*)(A + (size_t)r * K + (kt + 1) * BK + aCol) : z4;
            }
            #pragma unroll
            for (int i = 0; i < 2; i++) {
                size_t go = (size_t)((kt + 1) * BK + bR[i]) * N + blockN + bC[i];
                pbh[i] = *(const uint4*)(Bhi + go);
                pbl[i] = *(const uint4*)(Blo + go);
            }
        }

        #pragma unroll
        for (int ks = 0; ks < 2; ks++) {
            uint32_t ah[2][4], al[2][4];
            #pragma unroll
            for (int mt = 0; mt < 2; mt++) {
                uint32_t off = (uint32_t)((wm * 32 + mt * 16 + (lane & 15)) * (BK + APAD)
                                          + (lane >> 4) * 8 + ks * 16) * 2u;
                LDM4(ah[mt][0], ah[mt][1], ah[mt][2], ah[mt][3], baseAhi + off);
                LDM4(al[mt][0], al[mt][1], al[mt][2], al[mt][3], baseAlo + off);
            }
            uint32_t bh[8][2], bl[8][2];
            #pragma unroll
            for (int p = 0; p < 4; p++) {
                uint32_t off = (uint32_t)((ks * 16 + (lane & 15)) * (BN + BPAD)
                                          + wn * 64 + p * 16 + ((lane & 16) >> 1)) * 2u;
                uint32_t r0, r1, r2, r3;
                LDM4T(r0, r1, r2, r3, baseBhi + off);
                bh[2 * p][0] = r0; bh[2 * p][1] = r1;
                bh[2 * p + 1][0] = r2; bh[2 * p + 1][1] = r3;
                LDM4T(r0, r1, r2, r3, baseBlo + off);
                bl[2 * p][0] = r0; bl[2 * p][1] = r1;
                bl[2 * p + 1][0] = r2; bl[2 * p + 1][1] = r3;
            }
            #pragma unroll
            for (int mt = 0; mt < 2; mt++)
                #pragma unroll
                for (int nt = 0; nt < 8; nt++) {
                    MMA16816(acc[mt][nt], ah[mt], bh[nt]);
                    MMA16816(acc[mt][nt], ah[mt], bl[nt]);
                    MMA16816(acc[mt][nt], al[mt], bh[nt]);
                }
        }
        __syncthreads();

        if (kt + 1 < nT) {
            #pragma unroll
            for (int i = 0; i < 4; i++) {
                int r = aRow0 + 32 * i;
                split2(&sAhi[r][aCol],     &sAlo[r][aCol],     pa[i].x, pa[i].y);
                split2(&sAhi[r][aCol + 2], &sAlo[r][aCol + 2], pa[i].z, pa[i].w);
            }
            #pragma unroll
            for (int i = 0; i < 2; i++) {
                *(uint4*)&sBhi[bR[i]][bC[i]] = pbh[i];
                *(uint4*)&sBlo[bR[i]][bC[i]] = pbl[i];
            }
            __syncthreads();
        }
    }

    // epilogue
    #pragma unroll
    for (int mt = 0; mt < 2; mt++) {
        #pragma unroll
        for (int nt = 0; nt < 8; nt++) {
            int row = blockM + wm * 32 + mt * 16 + (lane >> 2);
            int col = blockN + wn * 64 + nt * 8 + (lane & 3) * 2;
            float2 v0 = make_float2(acc[mt][nt][0], acc[mt][nt][1]);
            float2 v1 = make_float2(acc[mt][nt][2], acc[mt][nt][3]);
            if (BIAS) {
                float2 bv = *(const float2*)(bias + col);
                v0.x += bv.x; v0.y += bv.y;
                v1.x += bv.x; v1.y += bv.y;
            }
            if (RELU) {
                v0.x = fmaxf(v0.x, 0.f); v0.y = fmaxf(v0.y, 0.f);
                v1.x = fmaxf(v1.x, 0.f); v1.y = fmaxf(v1.y, 0.f);
            }
            if (row < M)     *(float2*)(C + (size_t)row * N + col) = v0;
            if (row + 8 < M) *(float2*)(C + (size_t)(row + 8) * N + col) = v1;
        }
    }
}

// ---------------- GEMV kernels ----------------
__global__ void gemv_kernel(const float* __restrict__ A, const float* __restrict__ v,
                            float* __restrict__ out, int M, int K)
{
    int row = blockIdx.x * (blockDim.x >> 5) + (threadIdx.x >> 5);
    int lane = threadIdx.x & 31;
    if (row >= M) return;
    const float4* a4 = (const float4*)(A + (size_t)row * K);
    const float4* v4 = (const float4*)v;
    int K4 = K >> 2;
    float sum = 0.f;
    for (int k = lane; k < K4; k += 32) {
        float4 a = a4[k], b = v4[k];
        sum += a.x * b.x + a.y * b.y + a.z * b.z + a.w * b.w;
    }
    #pragma unroll
    for (int o = 16; o; o >>= 1) sum += __shfl_down_sync(0xffffffffu, sum, o);
    if (lane == 0) out[row] = sum;
}

__global__ void gemv2_kernel(const float* __restrict__ A,
                             const float* __restrict__ va, const float* __restrict__ vb,
                             float* __restrict__ oa, float* __restrict__ ob, int M, int K)
{
    int row = blockIdx.x * (blockDim.x >> 5) + (threadIdx.x >> 5);
    int lane = threadIdx.x & 31;
    if (row >= M) return;
    const float4* a4 = (const float4*)(A + (size_t)row * K);
    const float4* va4 = (const float4*)va;
    const float4* vb4 = (const float4*)vb;
    int K4 = K >> 2;
    float sa = 0.f, sb = 0.f;
    for (int k = lane; k < K4; k += 32) {
        float4 a = a4[k], u = va4[k], t = vb4[k];
        sa += a.x * u.x + a.y * u.y + a.z * u.z + a.w * u.w;
        sb += a.x * t.x + a.y * t.y + a.z * t.z + a.w * t.w;
    }
    #pragma unroll
    for (int o = 16; o; o >>= 1) {
        sa += __shfl_down_sync(0xffffffffu, sa, o);
        sb += __shfl_down_sync(0xffffffffu, sb, o);
    }
    if (lane == 0) { oa[row] = sa; ob[row] = sb; }
}

// ---------------- CSR build kernels ----------------
__global__ void zero_int_kernel(int* __restrict__ p, int n)
{
    int i = blockIdx.x * blockDim.x + threadIdx.x;
    if (i < n) p[i] = 0;
}
__global__ void zero_f_kernel(float* __restrict__ p, int n)
{
    int i = blockIdx.x * blockDim.x + threadIdx.x;
    if (i < n) p[i] = 0.f;
}
__global__ void hist_kernel(const int* __restrict__ dst, int* __restrict__ cnt, int E)
{
    int i = blockIdx.x * blockDim.x + threadIdx.x;
    if (i < E) atomicAdd(&cnt[dst[i]], 1);
}
__global__ void scan1_kernel(const int* __restrict__ cnt, int* __restrict__ rowptr,
                             int* __restrict__ bsum, int n)
{
    __shared__ int sm[512];
    int t = threadIdx.x;
    int idx = blockIdx.x * 512 + t;
    int v = (idx < n) ? cnt[idx] : 0;
    sm[t] = v;
    __syncthreads();
    for (int o = 1; o < 512; o <<= 1) {
        int a = (t >= o) ? sm[t - o] : 0;
        __syncthreads();
        sm[t] += a;
        __syncthreads();
    }
    if (idx < n) rowptr[idx + 1] = sm[t];
    if (t == 511) bsum[blockIdx.x] = sm[511];
}
__global__ void scan2_kernel(const int* __restrict__ bsum, int* __restrict__ boff, int nb)
{
    __shared__ int sm[128];
    int t = threadIdx.x;
    int v = (t < nb) ? bsum[t] : 0;
    sm[t] = v;
    __syncthreads();
    for (int o = 1; o < 128; o <<= 1) {
        int a = (t >= o) ? sm[t - o] : 0;
        __syncthreads();
        sm[t] += a;
        __syncthreads();
    }
    boff[t] = sm[t] - v;     // exclusive
}
__global__ void scan3_kernel(int* __restrict__ rowptr, const int* __restrict__ boff, int n)
{
    int idx = blockIdx.x * 512 + threadIdx.x;
    if (idx < n) rowptr[idx + 1] += boff[blockIdx.x];
    if (idx == 0) rowptr[0] = 0;
}
__global__ void copy_int_kernel(int* __restrict__ d, const int* __restrict__ s, int n)
{
    int i = blockIdx.x * blockDim.x + threadIdx.x;
    if (i < n) d[i] = s[i];
}
__global__ void fill_kernel(const int* __restrict__ src, const int* __restrict__ dst,
                            int* __restrict__ pos, int* __restrict__ perm,
                            int* __restrict__ csrc, int E)
{
    int i = blockIdx.x * blockDim.x + threadIdx.x;
    if (i >= E) return;
    int slot = atomicAdd(&pos[dst[i]], 1);
    perm[i] = slot;
    csrc[slot] = src[i];
}

// ---------------- edge alpha (no-max softmax: exp(e), sum via atomics) ----------------
__global__ void alpha_kernel(const int* __restrict__ src, const int* __restrict__ dst,
                             const float* __restrict__ as_, const float* __restrict__ ad_,
                             const int* __restrict__ perm, float* __restrict__ cw,
                             float* __restrict__ s, int E)
{
    int i = blockIdx.x * blockDim.x + threadIdx.x;
    if (i >= E) return;
    float v = as_[src[i]] + ad_[dst[i]];
    v = v > 0.f ? v : 0.2f * v;          // leaky_relu, slope 0.2
    float ex = expf(v);
    cw[perm[i]] = ex;
    atomicAdd(&s[dst[i]], ex);
}

// ---------------- per-node CSR aggregation (both lists), out = 2*bias + sums ----------------
template<int C>
__global__ void agg_kernel(const int* __restrict__ rp1, const int* __restrict__ cs1,
                           const float* __restrict__ cw1, const float* __restrict__ s1,
                           const int* __restrict__ rp2, const int* __restrict__ cs2,
                           const float* __restrict__ cw2, const float* __restrict__ s2,
                           const float* __restrict__ h, const float* __restrict__ bias,
                           float* __restrict__ out)
{
    int n = blockIdx.x;
    int c = threadIdx.x * 4;
    float4 b4 = *(const float4*)(bias + c);
    float4 acc = make_float4(2.f * b4.x, 2.f * b4.y, 2.f * b4.z, 2.f * b4.w);

    int st = rp1[n], en = rp1[n + 1];
    float inv = 1.f / (s1[n] + 1e-16f);
    for (int j = st; j < en; j++) {
        float wv = cw1[j] * inv;
        float4 hv = *(const float4*)(h + (size_t)cs1[j] * C + c);
        acc.x += wv * hv.x; acc.y += wv * hv.y;
        acc.z += wv * hv.z; acc.w += wv * hv.w;
    }
    st = rp2[n]; en = rp2[n + 1];
    inv = 1.f / (s2[n] + 1e-16f);
    for (int j = st; j < en; j++) {
        float wv = cw2[j] * inv;
        float4 hv = *(const float4*)(h + (size_t)cs2[j] * C + c);
        acc.x += wv * hv.x; acc.y += wv * hv.y;
        acc.z += wv * hv.z; acc.w += wv * hv.w;
    }
    *(float4*)(out + (size_t)n * C + c) = acc;
}

// ---------------- host orchestration ----------------
static void* symaddr(const void* s)
{
    void* p = nullptr;
    cudaGetSymbolAddress(&p, s);
    return p;
}

extern "C" void kernel_launch(void* const* d_in, const int* in_sizes, int n_in,
                              void* d_out, int out_size)
{
    (void)n_in; (void)out_size;
    const float* x   = (const float*)d_in[0];
    const int*   ei1 = (const int*)d_in[1];
    const int*   ei2 = (const int*)d_in[2];
    const float* W1s = (const float*)d_in[3];
    const float* W1d = (const float*)d_in[4];
    const float* a1s = (const float*)d_in[5];
    const float* a1d = (const float*)d_in[6];
    const float* b1  = (const float*)d_in[7];
    const float* Wl1 = (const float*)d_in[8];
    const float* bl1 = (const float*)d_in[9];
    const float* W2s = (const float*)d_in[10];
    const float* W2d = (const float*)d_in[11];
    const float* a2s = (const float*)d_in[12];
    const float* a2d = (const float*)d_in[13];
    const float* b2  = (const float*)d_in[14];
    const float* Wl2 = (const float*)d_in[15];
    const float* bl2 = (const float*)d_in[16];
    float* out = (float*)d_out;

    const int N = in_sizes[0] / DD;       // 50000
    const int E = in_sizes[1] / 2;        // 150000

    float* hsrc = (float*)symaddr(g_hsrc);
    float* agg  = (float*)symaddr(g_agg);
    float* hmid = (float*)symaddr(g_hmid);
    float* asrc = (float*)symaddr(g_asrc);
    float* adst = (float*)symaddr(g_adst);
    float* sbuf = (float*)symaddr(g_s);          // [2][NN]
    float* wa   = (float*)symaddr(g_wa);
    float* wb   = (float*)symaddr(g_wb);
    int* rowptr = (int*)symaddr(g_rowptr);       // [2][NN+1]
    int* pos    = (int*)symaddr(g_pos);          // [2][NN]
    int* perm   = (int*)symaddr(g_perm);         // [2][EE]
    int* csrc   = (int*)symaddr(g_csrc);         // [2][EE]
    float* cw   = (float*)symaddr(g_cw);         // [2][EE]
    int* bsum   = (int*)symaddr(g_bsum);         // [2][128]
    int* boff   = (int*)symaddr(g_boff);         // [2][128]
    __nv_bfloat16* whi = (__nv_bfloat16*)symaddr(g_whi);
    __nv_bfloat16* wlo = (__nv_bfloat16*)symaddr(g_wlo);

    const int NB = (NN + 511) / 512;             // scan blocks (98)

    // ---- pre-split weights (bf16 hi/lo, same [K,N] layout) ----
    wsplit_kernel<<<(DD * HH / 4 + 255) / 256, 256>>>(W1s, whi + WO1, wlo + WO1, DD * HH / 4);
    wsplit_kernel<<<(HH * HH / 4 + 255) / 256, 256>>>(Wl1, whi + WO2, wlo + WO2, HH * HH / 4);
    wsplit_kernel<<<(HH * OC / 4 + 255) / 256, 256>>>(W2s, whi + WO3, wlo + WO3, HH * OC / 4);
    wsplit_kernel<<<(OC * OC / 4 + 255) / 256, 256>>>(Wl2, whi + WO4, wlo + WO4, OC * OC / 4);

    // ---- build CSR for both edge lists (structure shared by both layers) ----
    zero_int_kernel<<<(2 * NN + 255) / 256, 256>>>(pos, 2 * NN);
    for (int l = 0; l < 2; l++) {
        const int* dstp = (l ? ei2 : ei1) + E;
        const int* srcp = (l ? ei2 : ei1);
        int* cnt_l = pos + l * NN;
        int* rp_l  = rowptr + l * (NN + 1);
        hist_kernel<<<(E + 255) / 256, 256>>>(dstp, cnt_l, E);
        scan1_kernel<<<NB, 512>>>(cnt_l, rp_l, bsum + l * 128, N);
        scan2_kernel<<<1, 128>>>(bsum + l * 128, boff + l * 128, NB);
        scan3_kernel<<<NB, 512>>>(rp_l, boff + l * 128, N);
        copy_int_kernel<<<(NN + 255) / 256, 256>>>(cnt_l, rp_l, N);   // pos = row starts
        fill_kernel<<<(E + 255) / 256, 256>>>(srcp, dstp, cnt_l, perm + l * EE, csrc + l * EE, E);
    }

    dim3 gH(HH / 128, (N + 127) / 128);
    dim3 gO(OC / 128, (N + 127) / 128);

    // ================= layer 1 (D=512 -> H=512) =================
    gemv_kernel<<<(DD + 7) / 8, 256>>>(W1s, a1s, wa, DD, HH);
    gemv_kernel<<<(DD + 7) / 8, 256>>>(W1d, a1d, wb, DD, HH);
    mma_gemm_kernel<false, false><<<gH, 256>>>(x, whi + WO1, wlo + WO1, nullptr, hsrc, N, HH, DD);
    gemv2_kernel<<<(N + 7) / 8, 256>>>(x, wa, wb, asrc, adst, N, DD);

    zero_f_kernel<<<(2 * NN + 255) / 256, 256>>>(sbuf, 2 * NN);
    for (int l = 0; l < 2; l++) {
        const int* srcp = (l ? ei2 : ei1);
        const int* dstp = srcp + E;
        alpha_kernel<<<(E + 255) / 256, 256>>>(srcp, dstp, asrc, adst,
                                               perm + l * EE, cw + l * EE, sbuf + l * NN, E);
    }
    agg_kernel<HH><<<N, HH / 4>>>(rowptr, csrc, cw, sbuf,
                                  rowptr + (NN + 1), csrc + EE, cw + EE, sbuf + NN,
                                  hsrc, b1, agg);

    // hmid = relu(agg @ Wl1 + bl1)
    mma_gemm_kernel<true, true><<<gH, 256>>>(agg, whi + WO2, wlo + WO2, bl1, hmid, N, HH, HH);

    // ================= layer 2 (H=512 -> O=256) =================
    gemv_kernel<<<(HH + 7) / 8, 256>>>(W2s, a2s, wa, HH, OC);
    gemv_kernel<<<(HH + 7) / 8, 256>>>(W2d, a2d, wb, HH, OC);
    mma_gemm_kernel<false, false><<<gO, 256>>>(hmid, whi + WO3, wlo + WO3, nullptr, hsrc, N, OC, HH);
    gemv2_kernel<<<(N + 7) / 8, 256>>>(hmid, wa, wb, asrc, adst, N, HH);

    zero_f_kernel<<<(2 * NN + 255) / 256, 256>>>(sbuf, 2 * NN);
    for (int l = 0; l < 2; l++) {
        const int* srcp = (l ? ei2 : ei1);
        const int* dstp = srcp + E;
        alpha_kernel<<<(E + 255) / 256, 256>>>(srcp, dstp, asrc, adst,
                                               perm + l * EE, cw + l * EE, sbuf + l * NN, E);
    }
    agg_kernel<OC><<<N, OC / 4>>>(rowptr, csrc, cw, sbuf,
                                  rowptr + (NN + 1), csrc + EE, cw + EE, sbuf + NN,
                                  hsrc, b2, agg);

    // out = agg @ Wl2 + bl2
    mma_gemm_kernel<true, false><<<gO, 256>>>(agg, whi + WO4, wlo + WO4, bl2, out, N, OC, OC);
}

// round 7
// speedup vs baseline: 3.9397x; 1.0618x over previous
#include <cuda_runtime.h>
#include <cuda_bf16.h>
#include <math_constants.h>
#include <cstdint>

// Problem constants (fixed by the reference setup)
#define NN  50000
#define DD  512
#define HH  512
#define OC  256
#define EE  150000

// ---------------- scratch (no allocation allowed -> __device__ globals) ----------------
__device__ float g_hsrc[(size_t)NN * HH];   // layer1: [N,512]; layer2 reuse: [N,256]
__device__ float g_agg [(size_t)NN * HH];   // conv accumulator
__device__ float g_hmid[(size_t)NN * HH];   // after lin1
__device__ float g_asrc[NN];
__device__ float g_adst[NN];
__device__ float g_s[4][NN];                // per-layer, per-list softmax sums
__device__ float g_wa[2][DD];
__device__ float g_wb[2][DD];

// CSR structures (built once per launch; shared by both layers)
__device__ int   g_rowptr[2][NN + 1];
__device__ int   g_pos[2][NN];              // histogram, then fill cursor
__device__ int   g_perm[2][EE];             // edge -> csr slot
__device__ int   g_csrc[2][EE];             // csr: source node per slot
__device__ float g_cw[2][EE];               // csr: exp(e) per slot (per layer)
__device__ int   g_bsum[2][128];
__device__ int   g_boff[2][128];

// pre-split weights, [K,N] fp32 layout -> bf16 hi/lo (same layout)
#define WO1 0
#define WO2 262144
#define WO3 524288
#define WO4 655360
#define WTOT 720896
__device__ __nv_bfloat16 g_whi[WTOT];
__device__ __nv_bfloat16 g_wlo[WTOT];

// ==================== weight bf16 hi/lo split (elementwise, float4) ====================
__global__ void wsplit_kernel(const float* __restrict__ W,
                              __nv_bfloat16* __restrict__ hi, __nv_bfloat16* __restrict__ lo,
                              int total4)
{
    int i = blockIdx.x * blockDim.x + threadIdx.x;
    if (i >= total4) return;
    float4 v = ((const float4*)W)[i];
    __nv_bfloat162 h0 = __floats2bfloat162_rn(v.x, v.y);
    float2 f0 = __bfloat1622float2(h0);
    __nv_bfloat162 l0 = __floats2bfloat162_rn(v.x - f0.x, v.y - f0.y);
    __nv_bfloat162 h1 = __floats2bfloat162_rn(v.z, v.w);
    float2 f1 = __bfloat1622float2(h1);
    __nv_bfloat162 l1 = __floats2bfloat162_rn(v.z - f1.x, v.w - f1.y);
    uint2 hh, ll;
    hh.x = reinterpret_cast<uint32_t&>(h0); hh.y = reinterpret_cast<uint32_t&>(h1);
    ll.x = reinterpret_cast<uint32_t&>(l0); ll.y = reinterpret_cast<uint32_t&>(l1);
    ((uint2*)hi)[i] = hh;
    ((uint2*)lo)[i] = ll;
}

// ==================== tensor-core GEMM (mma.sync, 3-term bf16 split) ====================
#define LDM4(r0,r1,r2,r3,addr) \
    asm volatile("ldmatrix.sync.aligned.m8n8.x4.shared.b16 {%0,%1,%2,%3}, [%4];" \
                 : "=r"(r0),"=r"(r1),"=r"(r2),"=r"(r3) : "r"(addr))
#define LDM4T(r0,r1,r2,r3,addr) \
    asm volatile("ldmatrix.sync.aligned.m8n8.x4.trans.shared.b16 {%0,%1,%2,%3}, [%4];" \
                 : "=r"(r0),"=r"(r1),"=r"(r2),"=r"(r3) : "r"(addr))
#define MMA16816(d, a, b) \
    asm volatile("mma.sync.aligned.m16n8k16.row.col.f32.bf16.bf16.f32 " \
                 "{%0,%1,%2,%3},{%4,%5,%6,%7},{%8,%9},{%0,%1,%2,%3};" \
                 : "+f"(d[0]),"+f"(d[1]),"+f"(d[2]),"+f"(d[3]) \
                 : "r"(a[0]),"r"(a[1]),"r"(a[2]),"r"(a[3]),"r"(b[0]),"r"(b[1]))

__device__ __forceinline__ uint32_t smem_u32(const void* p)
{
    return (uint32_t)__cvta_generic_to_shared(p);
}

__device__ __forceinline__ void split2(__nv_bfloat16* hp, __nv_bfloat16* lp, float x, float y)
{
    __nv_bfloat162 h = __floats2bfloat162_rn(x, y);
    float2 hf = __bfloat1622float2(h);
    __nv_bfloat162 l = __floats2bfloat162_rn(x - hf.x, y - hf.y);
    *(__nv_bfloat162*)hp = h;
    *(__nv_bfloat162*)lp = l;
}

// C = A[MxK](fp32, split on the fly) @ B[KxN](pre-split bf16 hi/lo) (+bias)(+relu)
template<bool BIAS, bool RELU>
__global__ __launch_bounds__(256)
void mma_gemm_kernel(const float* __restrict__ A,
                     const __nv_bfloat16* __restrict__ Bhi,
                     const __nv_bfloat16* __restrict__ Blo,
                     const float* __restrict__ bias, float* __restrict__ C,
                     int M, int N, int K)
{
    const int BM = 128, BN = 128, BK = 32;
    const int APAD = 8, BPAD = 8;
    __shared__ __align__(16) __nv_bfloat16 sAhi[BM][BK + APAD];
    __shared__ __align__(16) __nv_bfloat16 sAlo[BM][BK + APAD];
    __shared__ __align__(16) __nv_bfloat16 sBhi[BK][BN + BPAD];
    __shared__ __align__(16) __nv_bfloat16 sBlo[BK][BN + BPAD];

    int tid = threadIdx.x;
    int lane = tid & 31;
    int w = tid >> 5;
    int wm = w & 3;
    int wn = w >> 2;

    int blockM = blockIdx.y * BM;
    int blockN = blockIdx.x * BN;

    int aRow0 = tid >> 3;          // + 32*i
    int aCol  = (tid & 7) * 4;
    // B tile: 32 rows x 128 cols = 512 uint4-groups of 8 bf16; 2 groups per thread
    int bR[2], bC[2];
    #pragma unroll
    for (int i = 0; i < 2; i++) {
        int g = tid + 256 * i;
        bR[i] = g >> 4;            // 0..31
        bC[i] = (g & 15) * 8;      // 0..120
    }

    const float4 z4 = make_float4(0.f, 0.f, 0.f, 0.f);
    float4 pa[4];
    uint4 pbh[2], pbl[2];

    float acc[2][8][4];
    #pragma unroll
    for (int mt = 0; mt < 2; mt++)
        #pragma unroll
        for (int nt = 0; nt < 8; nt++)
            #pragma unroll
            for (int q = 0; q < 4; q++) acc[mt][nt][q] = 0.f;

    uint32_t baseAhi = smem_u32(&sAhi[0][0]);
    uint32_t baseAlo = smem_u32(&sAlo[0][0]);
    uint32_t baseBhi = smem_u32(&sBhi[0][0]);
    uint32_t baseBlo = smem_u32(&sBlo[0][0]);

    // prologue: tile 0
    #pragma unroll
    for (int i = 0; i < 4; i++) {
        int r = blockM + aRow0 + 32 * i;
        pa[i] = (r < M) ? *(const float4*)(A + (size_t)r * K + aCol) : z4;
    }
    #pragma unroll
    for (int i = 0; i < 2; i++) {
        size_t go = (size_t)bR[i] * N + blockN + bC[i];
        pbh[i] = *(const uint4*)(Bhi + go);
        pbl[i] = *(const uint4*)(Blo + go);
    }
    #pragma unroll
    for (int i = 0; i < 4; i++) {
        int r = aRow0 + 32 * i;
        split2(&sAhi[r][aCol],     &sAlo[r][aCol],     pa[i].x, pa[i].y);
        split2(&sAhi[r][aCol + 2], &sAlo[r][aCol + 2], pa[i].z, pa[i].w);
    }
    #pragma unroll
    for (int i = 0; i < 2; i++) {
        *(uint4*)&sBhi[bR[i]][bC[i]] = pbh[i];
        *(uint4*)&sBlo[bR[i]][bC[i]] = pbl[i];
    }
    __syncthreads();

    int nT = K / BK;
    for (int kt = 0; kt < nT; kt++) {
        // prefetch next tile to registers
        if (kt + 1 < nT) {
            #pragma unroll
            for (int i = 0; i < 4; i++) {
                int r = blockM + aRow0 + 32 * i;
                pa[i] = (r < M) ? *(const float4*)(A + (size_t)r * K + (kt + 1) * BK + aCol) : z4;
            }
            #pragma unroll
            for (int i = 0; i < 2; i++) {
                size_t go = (size_t)((kt + 1) * BK + bR[i]) * N + blockN + bC[i];
                pbh[i] = *(const uint4*)(Bhi + go);
                pbl[i] = *(const uint4*)(Blo + go);
            }
        }

        #pragma unroll
        for (int ks = 0; ks < 2; ks++) {
            uint32_t ah[2][4], al[2][4];
            #pragma unroll
            for (int mt = 0; mt < 2; mt++) {
                uint32_t off = (uint32_t)((wm * 32 + mt * 16 + (lane & 15)) * (BK + APAD)
                                          + (lane >> 4) * 8 + ks * 16) * 2u;
                LDM4(ah[mt][0], ah[mt][1], ah[mt][2], ah[mt][3], baseAhi + off);
                LDM4(al[mt][0], al[mt][1], al[mt][2], al[mt][3], baseAlo + off);
            }
            uint32_t bh[8][2], bl[8][2];
            #pragma unroll
            for (int p = 0; p < 4; p++) {
                uint32_t off = (uint32_t)((ks * 16 + (lane & 15)) * (BN + BPAD)
                                          + wn * 64 + p * 16 + ((lane & 16) >> 1)) * 2u;
                uint32_t r0, r1, r2, r3;
                LDM4T(r0, r1, r2, r3, baseBhi + off);
                bh[2 * p][0] = r0; bh[2 * p][1] = r1;
                bh[2 * p + 1][0] = r2; bh[2 * p + 1][1] = r3;
                LDM4T(r0, r1, r2, r3, baseBlo + off);
                bl[2 * p][0] = r0; bl[2 * p][1] = r1;
                bl[2 * p + 1][0] = r2; bl[2 * p + 1][1] = r3;
            }
            #pragma unroll
            for (int mt = 0; mt < 2; mt++)
                #pragma unroll
                for (int nt = 0; nt < 8; nt++) {
                    MMA16816(acc[mt][nt], ah[mt], bh[nt]);
                    MMA16816(acc[mt][nt], ah[mt], bl[nt]);
                    MMA16816(acc[mt][nt], al[mt], bh[nt]);
                }
        }
        __syncthreads();

        if (kt + 1 < nT) {
            #pragma unroll
            for (int i = 0; i < 4; i++) {
                int r = aRow0 + 32 * i;
                split2(&sAhi[r][aCol],     &sAlo[r][aCol],     pa[i].x, pa[i].y);
                split2(&sAhi[r][aCol + 2], &sAlo[r][aCol + 2], pa[i].z, pa[i].w);
            }
            #pragma unroll
            for (int i = 0; i < 2; i++) {
                *(uint4*)&sBhi[bR[i]][bC[i]] = pbh[i];
                *(uint4*)&sBlo[bR[i]][bC[i]] = pbl[i];
            }
            __syncthreads();
        }
    }

    // epilogue
    #pragma unroll
    for (int mt = 0; mt < 2; mt++) {
        #pragma unroll
        for (int nt = 0; nt < 8; nt++) {
            int row = blockM + wm * 32 + mt * 16 + (lane >> 2);
            int col = blockN + wn * 64 + nt * 8 + (lane & 3) * 2;
            float2 v0 = make_float2(acc[mt][nt][0], acc[mt][nt][1]);
            float2 v1 = make_float2(acc[mt][nt][2], acc[mt][nt][3]);
            if (BIAS) {
                float2 bv = *(const float2*)(bias + col);
                v0.x += bv.x; v0.y += bv.y;
                v1.x += bv.x; v1.y += bv.y;
            }
            if (RELU) {
                v0.x = fmaxf(v0.x, 0.f); v0.y = fmaxf(v0.y, 0.f);
                v1.x = fmaxf(v1.x, 0.f); v1.y = fmaxf(v1.y, 0.f);
            }
            if (row < M)     *(float2*)(C + (size_t)row * N + col) = v0;
            if (row + 8 < M) *(float2*)(C + (size_t)(row + 8) * N + col) = v1;
        }
    }
}

// ---------------- GEMV kernels ----------------
__global__ void gemv_kernel(const float* __restrict__ A, const float* __restrict__ v,
                            float* __restrict__ out, int M, int K)
{
    int row = blockIdx.x * (blockDim.x >> 5) + (threadIdx.x >> 5);
    int lane = threadIdx.x & 31;
    if (row >= M) return;
    const float4* a4 = (const float4*)(A + (size_t)row * K);
    const float4* v4 = (const float4*)v;
    int K4 = K >> 2;
    float sum = 0.f;
    for (int k = lane; k < K4; k += 32) {
        float4 a = a4[k], b = v4[k];
        sum += a.x * b.x + a.y * b.y + a.z * b.z + a.w * b.w;
    }
    #pragma unroll
    for (int o = 16; o; o >>= 1) sum += __shfl_down_sync(0xffffffffu, sum, o);
    if (lane == 0) out[row] = sum;
}

__global__ void gemv2_kernel(const float* __restrict__ A,
                             const float* __restrict__ va, const float* __restrict__ vb,
                             float* __restrict__ oa, float* __restrict__ ob, int M, int K)
{
    int row = blockIdx.x * (blockDim.x >> 5) + (threadIdx.x >> 5);
    int lane = threadIdx.x & 31;
    if (row >= M) return;
    const float4* a4 = (const float4*)(A + (size_t)row * K);
    const float4* va4 = (const float4*)va;
    const float4* vb4 = (const float4*)vb;
    int K4 = K >> 2;
    float sa = 0.f, sb = 0.f;
    for (int k = lane; k < K4; k += 32) {
        float4 a = a4[k], u = va4[k], t = vb4[k];
        sa += a.x * u.x + a.y * u.y + a.z * u.z + a.w * u.w;
        sb += a.x * t.x + a.y * t.y + a.z * t.z + a.w * t.w;
    }
    #pragma unroll
    for (int o = 16; o; o >>= 1) {
        sa += __shfl_down_sync(0xffffffffu, sa, o);
        sb += __shfl_down_sync(0xffffffffu, sb, o);
    }
    if (lane == 0) { oa[row] = sa; ob[row] = sb; }
}

// ---------------- CSR build kernels ----------------
__global__ void zero_int_kernel(int* __restrict__ p, int n)
{
    int i = blockIdx.x * blockDim.x + threadIdx.x;
    if (i < n) p[i] = 0;
}
__global__ void zero_f_kernel(float* __restrict__ p, int n)
{
    int i = blockIdx.x * blockDim.x + threadIdx.x;
    if (i < n) p[i] = 0.f;
}
__global__ void hist_kernel(const int* __restrict__ dst, int* __restrict__ cnt, int E)
{
    int i = blockIdx.x * blockDim.x + threadIdx.x;
    if (i < E) atomicAdd(&cnt[dst[i]], 1);
}
__global__ void scan1_kernel(const int* __restrict__ cnt, int* __restrict__ rowptr,
                             int* __restrict__ bsum, int n)
{
    __shared__ int sm[512];
    int t = threadIdx.x;
    int idx = blockIdx.x * 512 + t;
    int v = (idx < n) ? cnt[idx] : 0;
    sm[t] = v;
    __syncthreads();
    for (int o = 1; o < 512; o <<= 1) {
        int a = (t >= o) ? sm[t - o] : 0;
        __syncthreads();
        sm[t] += a;
        __syncthreads();
    }
    if (idx < n) rowptr[idx + 1] = sm[t];
    if (t == 511) bsum[blockIdx.x] = sm[511];
}
__global__ void scan2_kernel(const int* __restrict__ bsum, int* __restrict__ boff, int nb)
{
    __shared__ int sm[128];
    int t = threadIdx.x;
    int v = (t < nb) ? bsum[t] : 0;
    sm[t] = v;
    __syncthreads();
    for (int o = 1; o < 128; o <<= 1) {
        int a = (t >= o) ? sm[t - o] : 0;
        __syncthreads();
        sm[t] += a;
        __syncthreads();
    }
    boff[t] = sm[t] - v;     // exclusive
}
__global__ void scan3_kernel(int* __restrict__ rowptr, const int* __restrict__ boff, int n)
{
    int idx = blockIdx.x * 512 + threadIdx.x;
    if (idx < n) rowptr[idx + 1] += boff[blockIdx.x];
    if (idx == 0) rowptr[0] = 0;
}
__global__ void copy_int_kernel(int* __restrict__ d, const int* __restrict__ s, int n)
{
    int i = blockIdx.x * blockDim.x + threadIdx.x;
    if (i < n) d[i] = s[i];
}
__global__ void fill_kernel(const int* __restrict__ src, const int* __restrict__ dst,
                            int* __restrict__ pos, int* __restrict__ perm,
                            int* __restrict__ csrc, int E)
{
    int i = blockIdx.x * blockDim.x + threadIdx.x;
    if (i >= E) return;
    int slot = atomicAdd(&pos[dst[i]], 1);
    perm[i] = slot;
    csrc[slot] = src[i];
}

// ---------------- edge alpha, both lists in one kernel ----------------
// cw layout: [2][EE]; s: base for this layer, [2][NN]
__global__ void alpha_both_kernel(const int* __restrict__ src1, const int* __restrict__ dst1,
                                  const int* __restrict__ src2, const int* __restrict__ dst2,
                                  const float* __restrict__ as_, const float* __restrict__ ad_,
                                  const int* __restrict__ perm, float* __restrict__ cw,
                                  float* __restrict__ s, int E)
{
    int i = blockIdx.x * blockDim.x + threadIdx.x;
    if (i >= 2 * E) return;
    int l = (i >= E) ? 1 : 0;
    int j = i - l * E;
    const int* sp = l ? src2 : src1;
    const int* dp = l ? dst2 : dst1;
    int sn = sp[j], dn = dp[j];
    float v = as_[sn] + ad_[dn];
    v = v > 0.f ? v : 0.2f * v;          // leaky_relu, slope 0.2
    float ex = expf(v);
    cw[(size_t)l * EE + perm[(size_t)l * EE + j]] = ex;
    atomicAdd(&s[(size_t)l * NN + dn], ex);
}

// ---------------- per-node CSR aggregation (both lists), out = 2*bias + sums ----------------
template<int C>
__global__ void agg_kernel(const int* __restrict__ rp1, const int* __restrict__ cs1,
                           const float* __restrict__ cw1, const float* __restrict__ s1,
                           const int* __restrict__ rp2, const int* __restrict__ cs2,
                           const float* __restrict__ cw2, const float* __restrict__ s2,
                           const float* __restrict__ h, const float* __restrict__ bias,
                           float* __restrict__ out)
{
    int n = blockIdx.x;
    int c = threadIdx.x * 4;
    float4 b4 = *(const float4*)(bias + c);
    float4 acc = make_float4(2.f * b4.x, 2.f * b4.y, 2.f * b4.z, 2.f * b4.w);

    int st = rp1[n], en = rp1[n + 1];
    float inv = 1.f / (s1[n] + 1e-16f);
    for (int j = st; j < en; j++) {
        float wv = cw1[j] * inv;
        float4 hv = *(const float4*)(h + (size_t)cs1[j] * C + c);
        acc.x += wv * hv.x; acc.y += wv * hv.y;
        acc.z += wv * hv.z; acc.w += wv * hv.w;
    }
    st = rp2[n]; en = rp2[n + 1];
    inv = 1.f / (s2[n] + 1e-16f);
    for (int j = st; j < en; j++) {
        float wv = cw2[j] * inv;
        float4 hv = *(const float4*)(h + (size_t)cs2[j] * C + c);
        acc.x += wv * hv.x; acc.y += wv * hv.y;
        acc.z += wv * hv.z; acc.w += wv * hv.w;
    }
    *(float4*)(out + (size_t)n * C + c) = acc;
}

// ---------------- host orchestration ----------------
static void* symaddr(const void* s)
{
    void* p = nullptr;
    cudaGetSymbolAddress(&p, s);
    return p;
}

extern "C" void kernel_launch(void* const* d_in, const int* in_sizes, int n_in,
                              void* d_out, int out_size)
{
    (void)n_in; (void)out_size;
    const float* x   = (const float*)d_in[0];
    const int*   ei1 = (const int*)d_in[1];
    const int*   ei2 = (const int*)d_in[2];
    const float* W1s = (const float*)d_in[3];
    const float* W1d = (const float*)d_in[4];
    const float* a1s = (const float*)d_in[5];
    const float* a1d = (const float*)d_in[6];
    const float* b1  = (const float*)d_in[7];
    const float* Wl1 = (const float*)d_in[8];
    const float* bl1 = (const float*)d_in[9];
    const float* W2s = (const float*)d_in[10];
    const float* W2d = (const float*)d_in[11];
    const float* a2s = (const float*)d_in[12];
    const float* a2d = (const float*)d_in[13];
    const float* b2  = (const float*)d_in[14];
    const float* Wl2 = (const float*)d_in[15];
    const float* bl2 = (const float*)d_in[16];
    float* out = (float*)d_out;

    const int N = in_sizes[0] / DD;       // 50000
    const int E = in_sizes[1] / 2;        // 150000

    float* hsrc = (float*)symaddr(g_hsrc);
    float* agg  = (float*)symaddr(g_agg);
    float* hmid = (float*)symaddr(g_hmid);
    float* asrc = (float*)symaddr(g_asrc);
    float* adst = (float*)symaddr(g_adst);
    float* sbuf = (float*)symaddr(g_s);          // [4][NN]
    float* wa   = (float*)symaddr(g_wa);         // [2][DD]
    float* wb   = (float*)symaddr(g_wb);         // [2][DD]
    int* rowptr = (int*)symaddr(g_rowptr);       // [2][NN+1]
    int* pos    = (int*)symaddr(g_pos);          // [2][NN]
    int* perm   = (int*)symaddr(g_perm);         // [2][EE]
    int* csrc   = (int*)symaddr(g_csrc);         // [2][EE]
    float* cw   = (float*)symaddr(g_cw);         // [2][EE]
    int* bsum   = (int*)symaddr(g_bsum);         // [2][128]
    int* boff   = (int*)symaddr(g_boff);         // [2][128]
    __nv_bfloat16* whi = (__nv_bfloat16*)symaddr(g_whi);
    __nv_bfloat16* wlo = (__nv_bfloat16*)symaddr(g_wlo);

    const int NB = (NN + 511) / 512;             // scan blocks (98)
    const int* srcp1 = ei1;            const int* dstp1 = ei1 + E;
    const int* srcp2 = ei2;            const int* dstp2 = ei2 + E;

    // one-time streams/events (host-side objects; no device memory)
    static cudaStream_t sB = nullptr, sC = nullptr;
    static cudaEvent_t ev0, evB, evC, ev1, evC2;
    if (!sB) {
        cudaStreamCreateWithFlags(&sB, cudaStreamNonBlocking);
        cudaStreamCreateWithFlags(&sC, cudaStreamNonBlocking);
        cudaEventCreateWithFlags(&ev0, cudaEventDisableTiming);
        cudaEventCreateWithFlags(&evB, cudaEventDisableTiming);
        cudaEventCreateWithFlags(&evC, cudaEventDisableTiming);
        cudaEventCreateWithFlags(&ev1, cudaEventDisableTiming);
        cudaEventCreateWithFlags(&evC2, cudaEventDisableTiming);
    }

    dim3 gH(HH / 128, (N + 127) / 128);
    dim3 gO(OC / 128, (N + 127) / 128);

    // ===== fork =====
    cudaEventRecord(ev0, 0);
    cudaStreamWaitEvent(sB, ev0, 0);
    cudaStreamWaitEvent(sC, ev0, 0);

    // ----- stream B: weight splits (except W1s), L2 weight gemvs, CSR build, sum zeroing -----
    wsplit_kernel<<<(HH * HH / 4 + 255) / 256, 256, 0, sB>>>(Wl1, whi + WO2, wlo + WO2, HH * HH / 4);
    wsplit_kernel<<<(HH * OC / 4 + 255) / 256, 256, 0, sB>>>(W2s, whi + WO3, wlo + WO3, HH * OC / 4);
    wsplit_kernel<<<(OC * OC / 4 + 255) / 256, 256, 0, sB>>>(Wl2, whi + WO4, wlo + WO4, OC * OC / 4);
    gemv_kernel<<<(HH + 7) / 8, 256, 0, sB>>>(W2s, a2s, wa + DD, HH, OC);
    gemv_kernel<<<(HH + 7) / 8, 256, 0, sB>>>(W2d, a2d, wb + DD, HH, OC);
    zero_f_kernel<<<(4 * NN + 255) / 256, 256, 0, sB>>>(sbuf, 4 * NN);
    zero_int_kernel<<<(2 * NN + 255) / 256, 256, 0, sB>>>(pos, 2 * NN);
    for (int l = 0; l < 2; l++) {
        const int* dstp = l ? dstp2 : dstp1;
        const int* srcp = l ? srcp2 : srcp1;
        int* cnt_l = pos + l * NN;
        int* rp_l  = rowptr + l * (NN + 1);
        hist_kernel<<<(E + 255) / 256, 256, 0, sB>>>(dstp, cnt_l, E);
        scan1_kernel<<<NB, 512, 0, sB>>>(cnt_l, rp_l, bsum + l * 128, N);
        scan2_kernel<<<1, 128, 0, sB>>>(bsum + l * 128, boff + l * 128, NB);
        scan3_kernel<<<NB, 512, 0, sB>>>(rp_l, boff + l * 128, N);
        copy_int_kernel<<<(NN + 255) / 256, 256, 0, sB>>>(cnt_l, rp_l, N);
        fill_kernel<<<(E + 255) / 256, 256, 0, sB>>>(srcp, dstp, cnt_l, perm + l * EE, csrc + l * EE, E);
    }
    cudaEventRecord(evB, sB);

    // ----- stream C: L1 weight gemvs + node alphas from x -----
    gemv_kernel<<<(DD + 7) / 8, 256, 0, sC>>>(W1s, a1s, wa, DD, HH);
    gemv_kernel<<<(DD + 7) / 8, 256, 0, sC>>>(W1d, a1d, wb, DD, HH);
    gemv2_kernel<<<(N + 7) / 8, 256, 0, sC>>>(x, wa, wb, asrc, adst, N, DD);
    cudaEventRecord(evC, sC);

    // ----- default stream: critical chain -----
    wsplit_kernel<<<(DD * HH / 4 + 255) / 256, 256>>>(W1s, whi + WO1, wlo + WO1, DD * HH / 4);
    mma_gemm_kernel<false, false><<<gH, 256>>>(x, whi + WO1, wlo + WO1, nullptr, hsrc, N, HH, DD);

    cudaStreamWaitEvent(0, evB, 0);
    cudaStreamWaitEvent(0, evC, 0);
    alpha_both_kernel<<<(2 * E + 255) / 256, 256>>>(srcp1, dstp1, srcp2, dstp2,
                                                    asrc, adst, perm, cw, sbuf, E);
    agg_kernel<HH><<<N, HH / 4>>>(rowptr, csrc, cw, sbuf,
                                  rowptr + (NN + 1), csrc + EE, cw + EE, sbuf + NN,
                                  hsrc, b1, agg);
    mma_gemm_kernel<true, true><<<gH, 256>>>(agg, whi + WO2, wlo + WO2, bl1, hmid, N, HH, HH);

    // fork: layer-2 node alphas run parallel with GEMM2
    cudaEventRecord(ev1, 0);
    cudaStreamWaitEvent(sC, ev1, 0);
    gemv2_kernel<<<(N + 7) / 8, 256, 0, sC>>>(hmid, wa + DD, wb + DD, asrc, adst, N, HH);
    alpha_both_kernel<<<(2 * E + 255) / 256, 256, 0, sC>>>(srcp1, dstp1, srcp2, dstp2,
                                                           asrc, adst, perm, cw, sbuf + 2 * NN, E);
    cudaEventRecord(evC2, sC);

    mma_gemm_kernel<false, false><<<gO, 256>>>(hmid, whi + WO3, wlo + WO3, nullptr, hsrc, N, OC, HH);

    cudaStreamWaitEvent(0, evC2, 0);
    agg_kernel<OC><<<N, OC / 4>>>(rowptr, csrc, cw, sbuf + 2 * NN,
                                  rowptr + (NN + 1), csrc + EE, cw + EE, sbuf + 3 * NN,
                                  hsrc, b2, agg);
    mma_gemm_kernel<true, false><<<gO, 256>>>(agg, whi + WO4, wlo + WO4, bl2, out, N, OC, OC);
}